// round 12
// baseline (speedup 1.0000x reference)
#include <cuda_runtime.h>
#include <cstdint>

#define MAX_NODES 100000
#define MAX_EDGES 3200000
#define MAX_GRAPHS 512
#define HID 64
#define SCAN_B 256
#define KC 16            // GEMM k-chunk staged in smem
#define XS_STRIDE 132    // 128 rows + pad

// Scratch (static device globals)
__device__ __align__(16) float g_h  [MAX_NODES * HID];   // h_pre = (X@W)*dis
__device__ __align__(16) float g_o1 [MAX_NODES * HID];   // layer-1 out (relu'd)
__device__ __align__(16) float g_o2 [MAX_NODES * HID];   // layer-2 out (relu'd)
__device__ __align__(16) float g_dis[MAX_NODES];         // rsqrt(deg)
__device__ int g_src   [MAX_EDGES];
__device__ int g_dst   [MAX_EDGES];
__device__ __align__(16) int g_ssrc[MAX_EDGES];          // src sorted by dst (CSR)
__device__ int g_count [MAX_NODES];                      // in-degree (no self loop)
__device__ int g_rowst [MAX_NODES];                      // CSR row start
__device__ int g_cursor[MAX_NODES];
__device__ int g_bsum  [(MAX_NODES + SCAN_B - 1) / SCAN_B];
__device__ int g_boff  [(MAX_NODES + SCAN_B - 1) / SCAN_B];
__device__ int g_batch [MAX_NODES];
__device__ unsigned g_flags[2];

#define PACK2(dst, lo, hi) \
    asm("mov.b64 %0, {%1, %2};" : "=l"(dst) : "r"(__float_as_uint(lo)), "r"(__float_as_uint(hi)))
#define FMA2(acc, a, b) \
    asm("fma.rn.f32x2 %0, %1, %2, %0;" : "+l"(acc) : "l"(a), "l"(b))
#define MUL2(dst, a, b) \
    asm("mul.rn.f32x2 %0, %1, %2;" : "=l"(dst) : "l"(a), "l"(b))

// ---------------------------------------------------------------------------
// Launch 1: zero degree counters + dtype probe (int64 high words are zero).
__global__ void probe_init(const unsigned* __restrict__ ei_raw, int ei_count,
                           const unsigned* __restrict__ b_raw,  int b_count,
                           int n)
{
    int t = threadIdx.x;                       // 1024 threads, 1 block
    if (t < 2) g_flags[t] = 0u;
    for (int i = t; i < n; i += 1024) g_count[i] = 0;
    __syncthreads();
    unsigned acc0 = 0, acc1 = 0;
    for (int k = t; k < 2048; k += 1024) {
        int w0 = ei_count - 1 - 2 * k;
        if ((w0 & 1) == 0) w0 -= 1;
        if (w0 >= 1) acc0 |= ei_raw[w0];
        int w1 = b_count - 1 - 2 * k;
        if ((w1 & 1) == 0) w1 -= 1;
        if (w1 >= 1) acc1 |= b_raw[w1];
    }
    if (acc0) atomicOr(&g_flags[0], 1u);
    if (acc1) atomicOr(&g_flags[1], 1u);
}

// Launch 2: normalize indices to int32 + in-degree histogram + batch.
__global__ void convert_kernel(const void* __restrict__ ei_raw, int e,
                               const void* __restrict__ b_raw,  int n)
{
    int i = blockIdx.x * blockDim.x + threadIdx.x;
    bool ei32 = (g_flags[0] != 0u);
    bool b32  = (g_flags[1] != 0u);
    if (i < e) {
        int s, d;
        if (ei32) {
            s = ((const int*)ei_raw)[i];
            d = ((const int*)ei_raw)[e + i];
        } else {
            s = (int)((const long long*)ei_raw)[i];
            d = (int)((const long long*)ei_raw)[e + i];
        }
        s = min(max(s, 0), n - 1);
        d = min(max(d, 0), n - 1);
        g_src[i] = s;
        g_dst[i] = d;
        atomicAdd(&g_count[d], 1);
    }
    if (i < n) {
        int g = b32 ? ((const int*)b_raw)[i]
                    : (int)((const long long*)b_raw)[i];
        g_batch[i] = min(max(g, 0), MAX_GRAPHS - 1);
    }
}

// ---------------------------------------------------------------------------
// Launch 3: per-block scan sums + dis = rsqrt(deg+1).
__global__ void scan_a(int n) {
    __shared__ int s[SCAN_B];
    int i = blockIdx.x * SCAN_B + threadIdx.x;
    int v = (i < n) ? g_count[i] : 0;
    if (i < n) g_dis[i] = rsqrtf((float)v + 1.0f);
    s[threadIdx.x] = v;
    __syncthreads();
    for (int off = 1; off < SCAN_B; off <<= 1) {
        int t = (threadIdx.x >= off) ? s[threadIdx.x - off] : 0;
        __syncthreads();
        s[threadIdx.x] += t;
        __syncthreads();
    }
    if (threadIdx.x == SCAN_B - 1) g_bsum[blockIdx.x] = s[SCAN_B - 1];
}

__global__ void scan_b(int nb) {
    __shared__ int s[512];
    int t = threadIdx.x;
    int v = (t < nb) ? g_bsum[t] : 0;
    s[t] = v;
    __syncthreads();
    for (int off = 1; off < 512; off <<= 1) {
        int u = (t >= off) ? s[t - off] : 0;
        __syncthreads();
        s[t] += u;
        __syncthreads();
    }
    if (t < nb) g_boff[t] = s[t] - v;
}

__global__ void scan_c(int n) {
    __shared__ int s[SCAN_B];
    int i = blockIdx.x * SCAN_B + threadIdx.x;
    int v = (i < n) ? g_count[i] : 0;
    s[threadIdx.x] = v;
    __syncthreads();
    for (int off = 1; off < SCAN_B; off <<= 1) {
        int t = (threadIdx.x >= off) ? s[threadIdx.x - off] : 0;
        __syncthreads();
        s[threadIdx.x] += t;
        __syncthreads();
    }
    if (i < n) {
        int row = g_boff[blockIdx.x] + s[threadIdx.x] - v;
        g_rowst[i]  = row;
        g_cursor[i] = row;
    }
}

// Counting-sort scatter (CSR adjacency).
__global__ void scatter_kernel(int e) {
    int i = blockIdx.x * blockDim.x + threadIdx.x;
    if (i < e) {
        int d = g_dst[i];
        int pos = atomicAdd(&g_cursor[d], 1);
        g_ssrc[pos] = g_src[i];
    }
}

// ---------------------------------------------------------------------------
// Register-tiled GEMM with packed f32x2 FMA: h_pre = (X @ W) * dis[r].
// Block: 128 rows x 64 cols, 256 threads; thread tile = 4 rows x 8 cols
// (acc = 16 f32x2 = 32 regs). X staged transposed (conflict-free LDS).
template<int K>
__global__ __launch_bounds__(256)
void gcn_gemm(const float* __restrict__ X,
              const float* __restrict__ W,
              float* __restrict__ hout,
              int n)
{
    __shared__ __align__(16) float Ws[K * 64];
    __shared__ __align__(16) float Xs[KC][XS_STRIDE];

    int tid = threadIdx.x;
    int block_row = blockIdx.x * 128;
    int rg = tid >> 3;                 // 0..31 -> rows rg*4 .. rg*4+3
    int cg = tid & 7;                  // 0..7  -> cols cg*8 .. cg*8+7

    for (int i = tid; i < K * 16; i += 256)
        reinterpret_cast<float4*>(Ws)[i] = reinterpret_cast<const float4*>(W)[i];

    unsigned long long acc[16];        // acc[r*4+p] = cols (cg*8+2p, cg*8+2p+1)
    #pragma unroll
    for (int c = 0; c < 16; ++c) acc[c] = 0ULL;

    #pragma unroll
    for (int kc = 0; kc < K; kc += KC) {
        __syncthreads();               // Xs reuse safe; covers W on first iter
        #pragma unroll
        for (int p = 0; p < 2; ++p) {
            int row  = p * 64 + (tid >> 2);
            int c4   = (tid & 3) * 4;
            int grow = block_row + row;
            float4 v = make_float4(0.f, 0.f, 0.f, 0.f);
            if (grow < n)
                v = *reinterpret_cast<const float4*>(X + (size_t)grow * K + kc + c4);
            Xs[c4 + 0][row] = v.x;
            Xs[c4 + 1][row] = v.y;
            Xs[c4 + 2][row] = v.z;
            Xs[c4 + 3][row] = v.w;
        }
        __syncthreads();

        #pragma unroll
        for (int kk = 0; kk < KC; ++kk) {
            float4 xa = *reinterpret_cast<const float4*>(&Xs[kk][rg * 4]);
            float xr[4] = {xa.x, xa.y, xa.z, xa.w};

            const ulonglong2* wrow =
                reinterpret_cast<const ulonglong2*>(&Ws[(kc + kk) * 64 + cg * 8]);
            ulonglong2 wA = wrow[0];   // cols cg*8+0..3 as 2 f32x2
            ulonglong2 wB = wrow[1];   // cols cg*8+4..7

            #pragma unroll
            for (int r = 0; r < 4; ++r) {
                unsigned long long xp;
                PACK2(xp, xr[r], xr[r]);
                FMA2(acc[r * 4 + 0], xp, wA.x);
                FMA2(acc[r * 4 + 1], xp, wA.y);
                FMA2(acc[r * 4 + 2], xp, wB.x);
                FMA2(acc[r * 4 + 3], xp, wB.y);
            }
        }
    }

    // Epilogue: scale by dis[row] (packed), store 4 rows x 8 cols.
    #pragma unroll
    for (int r = 0; r < 4; ++r) {
        int grow = block_row + rg * 4 + r;
        if (grow >= n) continue;
        float ds = g_dis[grow];
        unsigned long long dsp;
        PACK2(dsp, ds, ds);
        unsigned long long* op =
            reinterpret_cast<unsigned long long*>(hout + (size_t)grow * HID + cg * 8);
        #pragma unroll
        for (int p = 0; p < 4; ++p) {
            unsigned long long t;
            MUL2(t, acc[r * 4 + p], dsp);
            op[p] = t;
        }
    }
}

// ---------------------------------------------------------------------------
// CSR aggregation: one warp per dst node, lane owns 2 channels (float2).
// Unroll 8 with up-front int4 index loads -> MLP 8 against L2 latency.
//   out[d] = relu( (h_pre[d] + sum_{s in row(d)} h_pre[s]) * dis[d] + b )
__global__ void agg_csr(const float* __restrict__ h,
                        const float* __restrict__ bias,
                        float* __restrict__ out,
                        int n)
{
    int warp = (blockIdx.x * blockDim.x + threadIdx.x) >> 5;
    int lane = threadIdx.x & 31;
    if (warp >= n) return;

    const float2* hp = reinterpret_cast<const float2*>(h);
    float2 acc = hp[warp * 32 + lane];        // self term
    float2 acc2 = make_float2(0.f, 0.f);
    int beg = g_rowst[warp];
    int end = beg + g_count[warp];

    int j = beg;
    while ((j & 3) && j < end) {              // align to int4
        int s = g_ssrc[j++];
        float2 v = hp[s * 32 + lane];
        acc.x += v.x; acc.y += v.y;
    }
    for (; j + 8 <= end; j += 8) {            // 8 independent gathers
        int4 i0 = *reinterpret_cast<const int4*>(&g_ssrc[j]);
        int4 i1 = *reinterpret_cast<const int4*>(&g_ssrc[j + 4]);
        float2 v0 = hp[i0.x * 32 + lane];
        float2 v1 = hp[i0.y * 32 + lane];
        float2 v2 = hp[i0.z * 32 + lane];
        float2 v3 = hp[i0.w * 32 + lane];
        float2 v4 = hp[i1.x * 32 + lane];
        float2 v5 = hp[i1.y * 32 + lane];
        float2 v6 = hp[i1.z * 32 + lane];
        float2 v7 = hp[i1.w * 32 + lane];
        acc.x  += (v0.x + v1.x) + (v2.x + v3.x);
        acc.y  += (v0.y + v1.y) + (v2.y + v3.y);
        acc2.x += (v4.x + v5.x) + (v6.x + v7.x);
        acc2.y += (v4.y + v5.y) + (v6.y + v7.y);
    }
    if (j + 4 <= end) {
        int4 i0 = *reinterpret_cast<const int4*>(&g_ssrc[j]);
        float2 v0 = hp[i0.x * 32 + lane];
        float2 v1 = hp[i0.y * 32 + lane];
        float2 v2 = hp[i0.z * 32 + lane];
        float2 v3 = hp[i0.w * 32 + lane];
        acc.x += (v0.x + v1.x) + (v2.x + v3.x);
        acc.y += (v0.y + v1.y) + (v2.y + v3.y);
        j += 4;
    }
    for (; j < end; ++j) {
        int s = g_ssrc[j];
        float2 v = hp[s * 32 + lane];
        acc.x += v.x; acc.y += v.y;
    }
    acc.x += acc2.x; acc.y += acc2.y;

    float ds = g_dis[warp];
    float2 b = __ldg(&reinterpret_cast<const float2*>(bias)[lane]);
    float2 o;
    o.x = fmaxf(fmaf(acc.x, ds, b.x), 0.f);
    o.y = fmaxf(fmaf(acc.y, ds, b.y), 0.f);
    reinterpret_cast<float2*>(out)[warp * 32 + lane] = o;
}

// ---------------------------------------------------------------------------
// Pool over sorted batch: one block per graph, binary-searched node range.
__global__ void pool_kernel(const float* __restrict__ o2,
                            float* __restrict__ out,
                            int n)
{
    int g = blockIdx.x;
    int c = threadIdx.x;                       // 64 threads = 64 channels

    int lo = 0, hi = n;
    while (lo < hi) { int m = (lo + hi) >> 1; if (g_batch[m] < g) lo = m + 1; else hi = m; }
    int start = lo;
    hi = n;
    while (lo < hi) { int m = (lo + hi) >> 1; if (g_batch[m] < g + 1) lo = m + 1; else hi = m; }
    int end = lo;

    float sum = 0.f;
    int i = start;
    for (; i + 3 < end; i += 4) {
        float a0 = o2[(size_t)i * HID + c];
        float a1 = o2[(size_t)(i + 1) * HID + c];
        float a2 = o2[(size_t)(i + 2) * HID + c];
        float a3 = o2[(size_t)(i + 3) * HID + c];
        sum += (a0 + a1) + (a2 + a3);
    }
    for (; i < end; ++i) sum += o2[(size_t)i * HID + c];

    out[g * HID + c] = sum / (float)max(end - start, 1);
}

// ---------------------------------------------------------------------------
extern "C" void kernel_launch(void* const* d_in, const int* in_sizes, int n_in,
                              void* d_out, int out_size)
{
    const float* x  = nullptr;
    const void  *ei = nullptr, *bt = nullptr;
    const float *W1 = nullptr, *W2 = nullptr, *b1 = nullptr, *b2 = nullptr;
    int n = 0, e = 0;

    long long maxsz = 0;
    for (int i = 0; i < n_in; ++i) if (in_sizes[i] > maxsz) maxsz = in_sizes[i];
    for (int i = 0; i < n_in; ++i)
        if (in_sizes[i] == maxsz && !x) { x = (const float*)d_in[i]; n = (int)(maxsz / 128); }
    for (int i = 0; i < n_in; ++i) {
        long long sz = in_sizes[i];
        const void* p = d_in[i];
        if (p == (const void*)x) continue;
        if (sz == (long long)n)      { bt = p; }
        else if (sz > (long long)n)  { ei = p; e = (int)(sz / 2); }
        else if (sz == 128 * 64)     { W1 = (const float*)p; }
        else if (sz == 64 * 64)      { W2 = (const float*)p; }
        else if (sz == 64)           { if (!b1) b1 = (const float*)p; else b2 = (const float*)p; }
    }

    float* out = (float*)d_out;
    const int ng = out_size / HID;

    float *ph, *po1, *po2;
    cudaGetSymbolAddress((void**)&ph,  g_h);
    cudaGetSymbolAddress((void**)&po1, g_o1);
    cudaGetSymbolAddress((void**)&po2, g_o2);

    const int T = 256;
    const int mx = (e > n ? e : n);
    const int nb = (n + SCAN_B - 1) / SCAN_B;
    const int gb = (n + 127) / 128;            // GEMM blocks (128 rows each)

    probe_init    <<<1, 1024>>>((const unsigned*)ei, 2 * e, (const unsigned*)bt, n, n);
    convert_kernel<<<(mx + T - 1) / T, T>>>(ei, e, bt, n);
    scan_a        <<<nb, SCAN_B>>>(n);                          // also computes dis

    gcn_gemm<128><<<gb, 256>>>(x, W1, ph, n);                   // 4th: profiled

    scan_b<<<1, 512>>>(nb);
    scan_c<<<nb, SCAN_B>>>(n);
    scatter_kernel<<<(e + T - 1) / T, T>>>(e);

    agg_csr<<<(n * 32 + T - 1) / T, T>>>(ph, b1, po1, n);

    gcn_gemm<64><<<gb, 256>>>(po1, W2, ph, n);
    agg_csr<<<(n * 32 + T - 1) / T, T>>>(ph, b2, po2, n);

    pool_kernel<<<ng, HID>>>(po2, out, n);
}

// round 13
// speedup vs baseline: 1.8319x; 1.8319x over previous
#include <cuda_runtime.h>
#include <cuda_fp16.h>
#include <cstdint>

#define MAX_NODES 100000
#define MAX_EDGES 3200000
#define MAX_GRAPHS 512
#define HID 64
#define SCAN_B 256

// Scratch (static device globals)
__device__ __align__(16) float g_h  [MAX_NODES * HID];   // h_pre = (X@W)*dis
__device__ __align__(16) float g_o1 [MAX_NODES * HID];   // layer-1 out (relu'd)
__device__ __align__(16) float g_o2 [MAX_NODES * HID];   // layer-2 out (relu'd)
__device__ __align__(16) float g_dis[MAX_NODES];         // rsqrt(deg)
__device__ int g_src   [MAX_EDGES];
__device__ int g_dst   [MAX_EDGES];
__device__ int g_ssrc  [MAX_EDGES];                      // src sorted by dst (CSR)
__device__ int g_count [MAX_NODES];                      // in-degree (no self loop)
__device__ int g_rowst [MAX_NODES];                      // CSR row start
__device__ int g_cursor[MAX_NODES];
__device__ int g_bsum  [(MAX_NODES + SCAN_B - 1) / SCAN_B];
__device__ int g_boff  [(MAX_NODES + SCAN_B - 1) / SCAN_B];
__device__ int g_batch [MAX_NODES];
__device__ unsigned g_flags[2];

// ---------------------------------------------------------------------------
// Launch 1: zero degree counters + dtype probe (int64 high words are zero).
__global__ void probe_init(const unsigned* __restrict__ ei_raw, int ei_count,
                           const unsigned* __restrict__ b_raw,  int b_count,
                           int n)
{
    int t = threadIdx.x;                       // 1024 threads, 1 block
    if (t < 2) g_flags[t] = 0u;
    for (int i = t; i < n; i += 1024) g_count[i] = 0;
    __syncthreads();
    unsigned acc0 = 0, acc1 = 0;
    for (int k = t; k < 2048; k += 1024) {
        int w0 = ei_count - 1 - 2 * k;
        if ((w0 & 1) == 0) w0 -= 1;
        if (w0 >= 1) acc0 |= ei_raw[w0];
        int w1 = b_count - 1 - 2 * k;
        if ((w1 & 1) == 0) w1 -= 1;
        if (w1 >= 1) acc1 |= b_raw[w1];
    }
    if (acc0) atomicOr(&g_flags[0], 1u);
    if (acc1) atomicOr(&g_flags[1], 1u);
}

// Launch 2: normalize indices to int32 + in-degree histogram + batch.
__global__ void convert_kernel(const void* __restrict__ ei_raw, int e,
                               const void* __restrict__ b_raw,  int n)
{
    int i = blockIdx.x * blockDim.x + threadIdx.x;
    bool ei32 = (g_flags[0] != 0u);
    bool b32  = (g_flags[1] != 0u);
    if (i < e) {
        int s, d;
        if (ei32) {
            s = ((const int*)ei_raw)[i];
            d = ((const int*)ei_raw)[e + i];
        } else {
            s = (int)((const long long*)ei_raw)[i];
            d = (int)((const long long*)ei_raw)[e + i];
        }
        s = min(max(s, 0), n - 1);
        d = min(max(d, 0), n - 1);
        g_src[i] = s;
        g_dst[i] = d;
        atomicAdd(&g_count[d], 1);
    }
    if (i < n) {
        int g = b32 ? ((const int*)b_raw)[i]
                    : (int)((const long long*)b_raw)[i];
        g_batch[i] = min(max(g, 0), MAX_GRAPHS - 1);
    }
}

// ---------------------------------------------------------------------------
// Launch 3: per-block scan sums + dis = rsqrt(deg+1).
__global__ void scan_a(int n) {
    __shared__ int s[SCAN_B];
    int i = blockIdx.x * SCAN_B + threadIdx.x;
    int v = (i < n) ? g_count[i] : 0;
    if (i < n) g_dis[i] = rsqrtf((float)v + 1.0f);
    s[threadIdx.x] = v;
    __syncthreads();
    for (int off = 1; off < SCAN_B; off <<= 1) {
        int t = (threadIdx.x >= off) ? s[threadIdx.x - off] : 0;
        __syncthreads();
        s[threadIdx.x] += t;
        __syncthreads();
    }
    if (threadIdx.x == SCAN_B - 1) g_bsum[blockIdx.x] = s[SCAN_B - 1];
}

__global__ void scan_b(int nb) {
    __shared__ int s[512];
    int t = threadIdx.x;
    int v = (t < nb) ? g_bsum[t] : 0;
    s[t] = v;
    __syncthreads();
    for (int off = 1; off < 512; off <<= 1) {
        int u = (t >= off) ? s[t - off] : 0;
        __syncthreads();
        s[t] += u;
        __syncthreads();
    }
    if (t < nb) g_boff[t] = s[t] - v;
}

__global__ void scan_c(int n) {
    __shared__ int s[SCAN_B];
    int i = blockIdx.x * SCAN_B + threadIdx.x;
    int v = (i < n) ? g_count[i] : 0;
    s[threadIdx.x] = v;
    __syncthreads();
    for (int off = 1; off < SCAN_B; off <<= 1) {
        int t = (threadIdx.x >= off) ? s[threadIdx.x - off] : 0;
        __syncthreads();
        s[threadIdx.x] += t;
        __syncthreads();
    }
    if (i < n) {
        int row = g_boff[blockIdx.x] + s[threadIdx.x] - v;
        g_rowst[i]  = row;
        g_cursor[i] = row;
    }
}

// Counting-sort scatter (CSR adjacency).
__global__ void scatter_kernel(int e) {
    int i = blockIdx.x * blockDim.x + threadIdx.x;
    if (i < e) {
        int d = g_dst[i];
        int pos = atomicAdd(&g_cursor[d], 1);
        g_ssrc[pos] = g_src[i];
    }
}

// ---------------------------------------------------------------------------
// Tensor-core GEMM: h_pre = (X @ W) * dis[r], fp16 inputs, fp32 accumulate.
// Block: 128 rows x 64 cols, 256 threads (8 warps). Warp = one m16 tile
// across all 64 cols (8 n8 tiles), mma.sync m16n8k16.
// X staged fp16 in 64-wide k-chunks; W staged fp16 TRANSPOSED (n-major) so
// B-fragment k-pairs are contiguous. Strides 72/136 halves => stride mod 64
// halves == 8 => conflict-free fragment loads.
template<int K>
__global__ __launch_bounds__(256)
void gcn_gemm(const float* __restrict__ X,
              const float* __restrict__ W,
              float* __restrict__ hout,
              int n)
{
    __shared__ __align__(16) __half Xh[128][72];      // 64-col chunk + pad
    __shared__ __align__(16) __half Wt[64][K + 8];    // transposed W (n-major)

    int tid  = threadIdx.x;
    int w    = tid >> 5;
    int lane = tid & 31;
    int gr   = lane >> 2;          // 0..7
    int qp   = lane & 3;           // quad pair 0..3
    int block_row = blockIdx.x * 128;

    // Stage Wt = W^T in fp16 (once).
    for (int i = tid; i < K * 64; i += 256) {
        int k = i >> 6, nn = i & 63;
        Wt[nn][k] = __float2half(W[i]);
    }

    float acc[8][4];
    #pragma unroll
    for (int nt = 0; nt < 8; ++nt)
        #pragma unroll
        for (int c = 0; c < 4; ++c) acc[nt][c] = 0.f;

    #pragma unroll
    for (int kc = 0; kc < K; kc += 64) {
        __syncthreads();           // Wt ready (first iter) / Xh reads done
        // Stage X chunk: 128 rows x 64 cols fp32 -> fp16.
        #pragma unroll
        for (int p = 0; p < 8; ++p) {
            int idx = p * 256 + tid;        // 2048 float4 groups
            int row = idx >> 4;
            int c4  = (idx & 15) << 2;
            int grow = block_row + row;
            float4 v = make_float4(0.f, 0.f, 0.f, 0.f);
            if (grow < n)
                v = *reinterpret_cast<const float4*>(X + (size_t)grow * K + kc + c4);
            *reinterpret_cast<__half2*>(&Xh[row][c4])     = __floats2half2_rn(v.x, v.y);
            *reinterpret_cast<__half2*>(&Xh[row][c4 + 2]) = __floats2half2_rn(v.z, v.w);
        }
        __syncthreads();

        #pragma unroll
        for (int ks = 0; ks < 4; ++ks) {
            // A fragment (m16k16, row-major): rows w*16+gr(+8), k-pairs.
            const __half* ar0 = &Xh[w * 16 + gr][ks * 16 + qp * 2];
            const __half* ar1 = &Xh[w * 16 + gr + 8][ks * 16 + qp * 2];
            unsigned a0 = *reinterpret_cast<const unsigned*>(ar0);
            unsigned a1 = *reinterpret_cast<const unsigned*>(ar1);
            unsigned a2 = *reinterpret_cast<const unsigned*>(ar0 + 8);
            unsigned a3 = *reinterpret_cast<const unsigned*>(ar1 + 8);

            #pragma unroll
            for (int nt = 0; nt < 8; ++nt) {
                // B fragment (k16n8, col-major): n = nt*8+gr, k-pairs contiguous in Wt.
                const __half* br = &Wt[nt * 8 + gr][kc + ks * 16 + qp * 2];
                unsigned b0 = *reinterpret_cast<const unsigned*>(br);
                unsigned b1 = *reinterpret_cast<const unsigned*>(br + 8);
                asm volatile(
                    "mma.sync.aligned.m16n8k16.row.col.f32.f16.f16.f32 "
                    "{%0,%1,%2,%3}, {%4,%5,%6,%7}, {%8,%9}, {%0,%1,%2,%3};"
                    : "+f"(acc[nt][0]), "+f"(acc[nt][1]),
                      "+f"(acc[nt][2]), "+f"(acc[nt][3])
                    : "r"(a0), "r"(a1), "r"(a2), "r"(a3), "r"(b0), "r"(b1));
            }
        }
    }

    // Epilogue: scale by dis[row], store. c0,c1 -> row gr; c2,c3 -> row gr+8.
    int r0 = block_row + w * 16 + gr;
    int r1 = r0 + 8;
    float ds0 = (r0 < n) ? g_dis[r0] : 0.f;
    float ds1 = (r1 < n) ? g_dis[r1] : 0.f;
    #pragma unroll
    for (int nt = 0; nt < 8; ++nt) {
        int c = nt * 8 + qp * 2;
        if (r0 < n) {
            float2 o = make_float2(acc[nt][0] * ds0, acc[nt][1] * ds0);
            *reinterpret_cast<float2*>(hout + (size_t)r0 * HID + c) = o;
        }
        if (r1 < n) {
            float2 o = make_float2(acc[nt][2] * ds1, acc[nt][3] * ds1);
            *reinterpret_cast<float2*>(hout + (size_t)r1 * HID + c) = o;
        }
    }
}

// ---------------------------------------------------------------------------
// CSR aggregation: one warp per dst node, lane owns 2 channels (float2).
//   out[d] = relu( (h_pre[d] + sum_{s in row(d)} h_pre[s]) * dis[d] + b )
__global__ void agg_csr(const float* __restrict__ h,
                        const float* __restrict__ bias,
                        float* __restrict__ out,
                        int n)
{
    int warp = (blockIdx.x * blockDim.x + threadIdx.x) >> 5;
    int lane = threadIdx.x & 31;
    if (warp >= n) return;

    const float2* hp = reinterpret_cast<const float2*>(h);
    float2 acc = hp[warp * 32 + lane];        // self term
    int beg = g_rowst[warp];
    int end = beg + g_count[warp];

    int j = beg;
    for (; j + 1 < end; j += 2) {
        int s0 = g_ssrc[j];
        int s1 = g_ssrc[j + 1];
        float2 v0 = hp[s0 * 32 + lane];
        float2 v1 = hp[s1 * 32 + lane];
        acc.x += v0.x + v1.x;
        acc.y += v0.y + v1.y;
    }
    if (j < end) {
        int s = g_ssrc[j];
        float2 v = hp[s * 32 + lane];
        acc.x += v.x; acc.y += v.y;
    }

    float ds = g_dis[warp];
    float bx = __ldg(&bias[lane * 2]);
    float by = __ldg(&bias[lane * 2 + 1]);
    float2 o;
    o.x = fmaxf(fmaf(acc.x, ds, bx), 0.f);
    o.y = fmaxf(fmaf(acc.y, ds, by), 0.f);
    reinterpret_cast<float2*>(out)[warp * 32 + lane] = o;
}

// ---------------------------------------------------------------------------
// Pool over sorted batch: one block per graph, binary-searched node range.
__global__ void pool_kernel(const float* __restrict__ o2,
                            float* __restrict__ out,
                            int n)
{
    int g = blockIdx.x;
    int c = threadIdx.x;                       // 64 threads = 64 channels

    int lo = 0, hi = n;
    while (lo < hi) { int m = (lo + hi) >> 1; if (g_batch[m] < g) lo = m + 1; else hi = m; }
    int start = lo;
    hi = n;
    while (lo < hi) { int m = (lo + hi) >> 1; if (g_batch[m] < g + 1) lo = m + 1; else hi = m; }
    int end = lo;

    float sum = 0.f;
    int i = start;
    for (; i + 3 < end; i += 4) {
        float a0 = o2[(size_t)i * HID + c];
        float a1 = o2[(size_t)(i + 1) * HID + c];
        float a2 = o2[(size_t)(i + 2) * HID + c];
        float a3 = o2[(size_t)(i + 3) * HID + c];
        sum += (a0 + a1) + (a2 + a3);
    }
    for (; i < end; ++i) sum += o2[(size_t)i * HID + c];

    out[g * HID + c] = sum / (float)max(end - start, 1);
}

// ---------------------------------------------------------------------------
extern "C" void kernel_launch(void* const* d_in, const int* in_sizes, int n_in,
                              void* d_out, int out_size)
{
    const float* x  = nullptr;
    const void  *ei = nullptr, *bt = nullptr;
    const float *W1 = nullptr, *W2 = nullptr, *b1 = nullptr, *b2 = nullptr;
    int n = 0, e = 0;

    long long maxsz = 0;
    for (int i = 0; i < n_in; ++i) if (in_sizes[i] > maxsz) maxsz = in_sizes[i];
    for (int i = 0; i < n_in; ++i)
        if (in_sizes[i] == maxsz && !x) { x = (const float*)d_in[i]; n = (int)(maxsz / 128); }
    for (int i = 0; i < n_in; ++i) {
        long long sz = in_sizes[i];
        const void* p = d_in[i];
        if (p == (const void*)x) continue;
        if (sz == (long long)n)      { bt = p; }
        else if (sz > (long long)n)  { ei = p; e = (int)(sz / 2); }
        else if (sz == 128 * 64)     { W1 = (const float*)p; }
        else if (sz == 64 * 64)      { W2 = (const float*)p; }
        else if (sz == 64)           { if (!b1) b1 = (const float*)p; else b2 = (const float*)p; }
    }

    float* out = (float*)d_out;
    const int ng = out_size / HID;

    float *ph, *po1, *po2;
    cudaGetSymbolAddress((void**)&ph,  g_h);
    cudaGetSymbolAddress((void**)&po1, g_o1);
    cudaGetSymbolAddress((void**)&po2, g_o2);

    const int T = 256;
    const int mx = (e > n ? e : n);
    const int nb = (n + SCAN_B - 1) / SCAN_B;
    const int gb = (n + 127) / 128;            // GEMM blocks (128 rows each)

    probe_init    <<<1, 1024>>>((const unsigned*)ei, 2 * e, (const unsigned*)bt, n, n);
    convert_kernel<<<(mx + T - 1) / T, T>>>(ei, e, bt, n);
    scan_a        <<<nb, SCAN_B>>>(n);                          // also computes dis

    gcn_gemm<128><<<gb, 256>>>(x, W1, ph, n);                   // 4th: profiled

    scan_b<<<1, 512>>>(nb);
    scan_c<<<nb, SCAN_B>>>(n);
    scatter_kernel<<<(e + T - 1) / T, T>>>(e);

    agg_csr<<<(n * 32 + T - 1) / T, T>>>(ph, b1, po1, n);

    gcn_gemm<64><<<gb, 256>>>(po1, W2, ph, n);
    agg_csr<<<(n * 32 + T - 1) / T, T>>>(ph, b2, po2, n);

    pool_kernel<<<ng, HID>>>(po2, out, n);
}

// round 14
// speedup vs baseline: 1.9799x; 1.0808x over previous
#include <cuda_runtime.h>
#include <cuda_fp16.h>
#include <cstdint>

#define MAX_NODES 100000
#define MAX_EDGES 3200000
#define MAX_GRAPHS 512
#define HID 64
#define SCAN_B 256

// Scratch (static device globals)
__device__ __align__(16) __half g_h [MAX_NODES * HID];   // h_pre = (X@W)*dis, fp16
__device__ __align__(16) float g_o1 [MAX_NODES * HID];   // layer-1 out (relu'd)
__device__ __align__(16) float g_o2 [MAX_NODES * HID];   // layer-2 out (relu'd)
__device__ __align__(16) float g_dis[MAX_NODES];         // rsqrt(deg)
__device__ int g_src   [MAX_EDGES];
__device__ int g_dst   [MAX_EDGES];
__device__ int g_ssrc  [MAX_EDGES];                      // src sorted by dst (CSR)
__device__ int g_count [MAX_NODES];                      // in-degree (no self loop)
__device__ int g_rowst [MAX_NODES];                      // CSR row start
__device__ int g_cursor[MAX_NODES];
__device__ int g_bsum  [(MAX_NODES + SCAN_B - 1) / SCAN_B];
__device__ int g_boff  [(MAX_NODES + SCAN_B - 1) / SCAN_B];
__device__ int g_batch [MAX_NODES];
__device__ unsigned g_flags[2];

// ---------------------------------------------------------------------------
// Launch 1: zero degree counters + dtype probe (int64 high words are zero).
__global__ void probe_init(const unsigned* __restrict__ ei_raw, int ei_count,
                           const unsigned* __restrict__ b_raw,  int b_count,
                           int n)
{
    int t = threadIdx.x;                       // 1024 threads, 1 block
    if (t < 2) g_flags[t] = 0u;
    for (int i = t; i < n; i += 1024) g_count[i] = 0;
    __syncthreads();
    unsigned acc0 = 0, acc1 = 0;
    for (int k = t; k < 2048; k += 1024) {
        int w0 = ei_count - 1 - 2 * k;
        if ((w0 & 1) == 0) w0 -= 1;
        if (w0 >= 1) acc0 |= ei_raw[w0];
        int w1 = b_count - 1 - 2 * k;
        if ((w1 & 1) == 0) w1 -= 1;
        if (w1 >= 1) acc1 |= b_raw[w1];
    }
    if (acc0) atomicOr(&g_flags[0], 1u);
    if (acc1) atomicOr(&g_flags[1], 1u);
}

// Launch 2: normalize indices to int32 + in-degree histogram + batch.
__global__ void convert_kernel(const void* __restrict__ ei_raw, int e,
                               const void* __restrict__ b_raw,  int n)
{
    int i = blockIdx.x * blockDim.x + threadIdx.x;
    bool ei32 = (g_flags[0] != 0u);
    bool b32  = (g_flags[1] != 0u);
    if (i < e) {
        int s, d;
        if (ei32) {
            s = ((const int*)ei_raw)[i];
            d = ((const int*)ei_raw)[e + i];
        } else {
            s = (int)((const long long*)ei_raw)[i];
            d = (int)((const long long*)ei_raw)[e + i];
        }
        s = min(max(s, 0), n - 1);
        d = min(max(d, 0), n - 1);
        g_src[i] = s;
        g_dst[i] = d;
        atomicAdd(&g_count[d], 1);
    }
    if (i < n) {
        int g = b32 ? ((const int*)b_raw)[i]
                    : (int)((const long long*)b_raw)[i];
        g_batch[i] = min(max(g, 0), MAX_GRAPHS - 1);
    }
}

// ---------------------------------------------------------------------------
// Launch 3: per-block scan sums + dis = rsqrt(deg+1).
__global__ void scan_a(int n) {
    __shared__ int s[SCAN_B];
    int i = blockIdx.x * SCAN_B + threadIdx.x;
    int v = (i < n) ? g_count[i] : 0;
    if (i < n) g_dis[i] = rsqrtf((float)v + 1.0f);
    s[threadIdx.x] = v;
    __syncthreads();
    for (int off = 1; off < SCAN_B; off <<= 1) {
        int t = (threadIdx.x >= off) ? s[threadIdx.x - off] : 0;
        __syncthreads();
        s[threadIdx.x] += t;
        __syncthreads();
    }
    if (threadIdx.x == SCAN_B - 1) g_bsum[blockIdx.x] = s[SCAN_B - 1];
}

__global__ void scan_b(int nb) {
    __shared__ int s[512];
    int t = threadIdx.x;
    int v = (t < nb) ? g_bsum[t] : 0;
    s[t] = v;
    __syncthreads();
    for (int off = 1; off < 512; off <<= 1) {
        int u = (t >= off) ? s[t - off] : 0;
        __syncthreads();
        s[t] += u;
        __syncthreads();
    }
    if (t < nb) g_boff[t] = s[t] - v;
}

__global__ void scan_c(int n) {
    __shared__ int s[SCAN_B];
    int i = blockIdx.x * SCAN_B + threadIdx.x;
    int v = (i < n) ? g_count[i] : 0;
    s[threadIdx.x] = v;
    __syncthreads();
    for (int off = 1; off < SCAN_B; off <<= 1) {
        int t = (threadIdx.x >= off) ? s[threadIdx.x - off] : 0;
        __syncthreads();
        s[threadIdx.x] += t;
        __syncthreads();
    }
    if (i < n) {
        int row = g_boff[blockIdx.x] + s[threadIdx.x] - v;
        g_rowst[i]  = row;
        g_cursor[i] = row;
    }
}

// Counting-sort scatter (CSR adjacency).
__global__ void scatter_kernel(int e) {
    int i = blockIdx.x * blockDim.x + threadIdx.x;
    if (i < e) {
        int d = g_dst[i];
        int pos = atomicAdd(&g_cursor[d], 1);
        g_ssrc[pos] = g_src[i];
    }
}

// ---------------------------------------------------------------------------
// Tensor-core GEMM: h_pre = (X @ W) * dis[r], fp16 in/out, fp32 accumulate.
// Block: 128 rows x 64 cols, 256 threads (8 warps). mma.sync m16n8k16.
template<int K>
__global__ __launch_bounds__(256)
void gcn_gemm(const float* __restrict__ X,
              const float* __restrict__ W,
              __half* __restrict__ hout,
              int n)
{
    __shared__ __align__(16) __half Xh[128][72];      // 64-col chunk + pad
    __shared__ __align__(16) __half Wt[64][K + 8];    // transposed W (n-major)

    int tid  = threadIdx.x;
    int w    = tid >> 5;
    int lane = tid & 31;
    int gr   = lane >> 2;          // 0..7
    int qp   = lane & 3;           // quad pair 0..3
    int block_row = blockIdx.x * 128;

    for (int i = tid; i < K * 64; i += 256) {
        int k = i >> 6, nn = i & 63;
        Wt[nn][k] = __float2half(W[i]);
    }

    float acc[8][4];
    #pragma unroll
    for (int nt = 0; nt < 8; ++nt)
        #pragma unroll
        for (int c = 0; c < 4; ++c) acc[nt][c] = 0.f;

    #pragma unroll
    for (int kc = 0; kc < K; kc += 64) {
        __syncthreads();
        #pragma unroll
        for (int p = 0; p < 8; ++p) {
            int idx = p * 256 + tid;
            int row = idx >> 4;
            int c4  = (idx & 15) << 2;
            int grow = block_row + row;
            float4 v = make_float4(0.f, 0.f, 0.f, 0.f);
            if (grow < n)
                v = *reinterpret_cast<const float4*>(X + (size_t)grow * K + kc + c4);
            *reinterpret_cast<__half2*>(&Xh[row][c4])     = __floats2half2_rn(v.x, v.y);
            *reinterpret_cast<__half2*>(&Xh[row][c4 + 2]) = __floats2half2_rn(v.z, v.w);
        }
        __syncthreads();

        #pragma unroll
        for (int ks = 0; ks < 4; ++ks) {
            const __half* ar0 = &Xh[w * 16 + gr][ks * 16 + qp * 2];
            const __half* ar1 = &Xh[w * 16 + gr + 8][ks * 16 + qp * 2];
            unsigned a0 = *reinterpret_cast<const unsigned*>(ar0);
            unsigned a1 = *reinterpret_cast<const unsigned*>(ar1);
            unsigned a2 = *reinterpret_cast<const unsigned*>(ar0 + 8);
            unsigned a3 = *reinterpret_cast<const unsigned*>(ar1 + 8);

            #pragma unroll
            for (int nt = 0; nt < 8; ++nt) {
                const __half* br = &Wt[nt * 8 + gr][kc + ks * 16 + qp * 2];
                unsigned b0 = *reinterpret_cast<const unsigned*>(br);
                unsigned b1 = *reinterpret_cast<const unsigned*>(br + 8);
                asm volatile(
                    "mma.sync.aligned.m16n8k16.row.col.f32.f16.f16.f32 "
                    "{%0,%1,%2,%3}, {%4,%5,%6,%7}, {%8,%9}, {%0,%1,%2,%3};"
                    : "+f"(acc[nt][0]), "+f"(acc[nt][1]),
                      "+f"(acc[nt][2]), "+f"(acc[nt][3])
                    : "r"(a0), "r"(a1), "r"(a2), "r"(a3), "r"(b0), "r"(b1));
            }
        }
    }

    // Epilogue: scale by dis[row], store fp16. c0,c1 -> row gr; c2,c3 -> gr+8.
    int r0 = block_row + w * 16 + gr;
    int r1 = r0 + 8;
    float ds0 = (r0 < n) ? g_dis[r0] : 0.f;
    float ds1 = (r1 < n) ? g_dis[r1] : 0.f;
    #pragma unroll
    for (int nt = 0; nt < 8; ++nt) {
        int c = nt * 8 + qp * 2;
        if (r0 < n)
            *reinterpret_cast<__half2*>(hout + (size_t)r0 * HID + c) =
                __floats2half2_rn(acc[nt][0] * ds0, acc[nt][1] * ds0);
        if (r1 < n)
            *reinterpret_cast<__half2*>(hout + (size_t)r1 * HID + c) =
                __floats2half2_rn(acc[nt][2] * ds1, acc[nt][3] * ds1);
    }
}

// ---------------------------------------------------------------------------
// CSR aggregation, fp16 gather / fp32 accumulate, PAIRED EDGES:
// lanes 0-15 gather edge j's 128B row, lanes 16-31 edge j+1's.
// Per edge: 0.5 LDG requests, 1 L2 line, 128 B. Lane owns 4 channels.
//   out[d] = relu( (h[d] + sum_{s in row(d)} h[s]) * dis[d] + b )
__global__ void agg_csr(const __half* __restrict__ h,
                        const float* __restrict__ bias,
                        float* __restrict__ out,
                        int n)
{
    int warp = (blockIdx.x * blockDim.x + threadIdx.x) >> 5;
    int lane = threadIdx.x & 31;
    if (warp >= n) return;

    const uint2* hp = reinterpret_cast<const uint2*>(h);   // node row = 16 uint2
    int half = lane >> 4;
    int ch   = lane & 15;

    float4 acc = make_float4(0.f, 0.f, 0.f, 0.f);
#define ADDV(v) do {                                                   \
        __half2 _h0 = *reinterpret_cast<const __half2*>(&(v).x);      \
        __half2 _h1 = *reinterpret_cast<const __half2*>(&(v).y);      \
        float2 _f0 = __half22float2(_h0), _f1 = __half22float2(_h1);  \
        acc.x += _f0.x; acc.y += _f0.y; acc.z += _f1.x; acc.w += _f1.y; \
    } while (0)

    if (half == 0) { uint2 sv = hp[(size_t)warp * 16 + ch]; ADDV(sv); }

    int beg = g_rowst[warp];
    int end = beg + g_count[warp];

    int j = beg;
    for (; j + 3 < end; j += 4) {             // 2 paired gathers in flight
        int s0 = g_ssrc[j + half];
        int s1 = g_ssrc[j + 2 + half];
        uint2 v0 = hp[(size_t)s0 * 16 + ch];
        uint2 v1 = hp[(size_t)s1 * 16 + ch];
        ADDV(v0);
        ADDV(v1);
    }
    for (; j < end; j += 2) {
        int idx = j + half;
        if (idx < end) {
            int s = g_ssrc[idx];
            uint2 v = hp[(size_t)s * 16 + ch];
            ADDV(v);
        }
    }
#undef ADDV

    // Combine halves (lane i += lane i^16).
    acc.x += __shfl_xor_sync(0xffffffffu, acc.x, 16);
    acc.y += __shfl_xor_sync(0xffffffffu, acc.y, 16);
    acc.z += __shfl_xor_sync(0xffffffffu, acc.z, 16);
    acc.w += __shfl_xor_sync(0xffffffffu, acc.w, 16);

    if (half == 0) {
        float ds = g_dis[warp];
        float4 b = __ldg(&reinterpret_cast<const float4*>(bias)[ch]);
        float4 o;
        o.x = fmaxf(fmaf(acc.x, ds, b.x), 0.f);
        o.y = fmaxf(fmaf(acc.y, ds, b.y), 0.f);
        o.z = fmaxf(fmaf(acc.z, ds, b.z), 0.f);
        o.w = fmaxf(fmaf(acc.w, ds, b.w), 0.f);
        reinterpret_cast<float4*>(out)[(size_t)warp * 16 + ch] = o;
    }
}

// ---------------------------------------------------------------------------
// Pool over sorted batch: one block per graph, binary-searched node range.
__global__ void pool_kernel(const float* __restrict__ o2,
                            float* __restrict__ out,
                            int n)
{
    int g = blockIdx.x;
    int c = threadIdx.x;                       // 64 threads = 64 channels

    int lo = 0, hi = n;
    while (lo < hi) { int m = (lo + hi) >> 1; if (g_batch[m] < g) lo = m + 1; else hi = m; }
    int start = lo;
    hi = n;
    while (lo < hi) { int m = (lo + hi) >> 1; if (g_batch[m] < g + 1) lo = m + 1; else hi = m; }
    int end = lo;

    float sum = 0.f;
    int i = start;
    for (; i + 3 < end; i += 4) {
        float a0 = o2[(size_t)i * HID + c];
        float a1 = o2[(size_t)(i + 1) * HID + c];
        float a2 = o2[(size_t)(i + 2) * HID + c];
        float a3 = o2[(size_t)(i + 3) * HID + c];
        sum += (a0 + a1) + (a2 + a3);
    }
    for (; i < end; ++i) sum += o2[(size_t)i * HID + c];

    out[g * HID + c] = sum / (float)max(end - start, 1);
}

// ---------------------------------------------------------------------------
extern "C" void kernel_launch(void* const* d_in, const int* in_sizes, int n_in,
                              void* d_out, int out_size)
{
    const float* x  = nullptr;
    const void  *ei = nullptr, *bt = nullptr;
    const float *W1 = nullptr, *W2 = nullptr, *b1 = nullptr, *b2 = nullptr;
    int n = 0, e = 0;

    long long maxsz = 0;
    for (int i = 0; i < n_in; ++i) if (in_sizes[i] > maxsz) maxsz = in_sizes[i];
    for (int i = 0; i < n_in; ++i)
        if (in_sizes[i] == maxsz && !x) { x = (const float*)d_in[i]; n = (int)(maxsz / 128); }
    for (int i = 0; i < n_in; ++i) {
        long long sz = in_sizes[i];
        const void* p = d_in[i];
        if (p == (const void*)x) continue;
        if (sz == (long long)n)      { bt = p; }
        else if (sz > (long long)n)  { ei = p; e = (int)(sz / 2); }
        else if (sz == 128 * 64)     { W1 = (const float*)p; }
        else if (sz == 64 * 64)      { W2 = (const float*)p; }
        else if (sz == 64)           { if (!b1) b1 = (const float*)p; else b2 = (const float*)p; }
    }

    float* out = (float*)d_out;
    const int ng = out_size / HID;

    __half* ph;
    float *po1, *po2;
    cudaGetSymbolAddress((void**)&ph,  g_h);
    cudaGetSymbolAddress((void**)&po1, g_o1);
    cudaGetSymbolAddress((void**)&po2, g_o2);

    const int T = 256;
    const int mx = (e > n ? e : n);
    const int nb = (n + SCAN_B - 1) / SCAN_B;
    const int gb = (n + 127) / 128;            // GEMM blocks (128 rows each)

    probe_init    <<<1, 1024>>>((const unsigned*)ei, 2 * e, (const unsigned*)bt, n, n);
    convert_kernel<<<(mx + T - 1) / T, T>>>(ei, e, bt, n);
    scan_a        <<<nb, SCAN_B>>>(n);                          // also computes dis

    gcn_gemm<128><<<gb, 256>>>(x, W1, ph, n);                   // 4th: profiled

    scan_b<<<1, 512>>>(nb);
    scan_c<<<nb, SCAN_B>>>(n);
    scatter_kernel<<<(e + T - 1) / T, T>>>(e);

    agg_csr<<<(n * 32 + T - 1) / T, T>>>(ph, b1, po1, n);

    gcn_gemm<64><<<gb, 256>>>(po1, W2, ph, n);
    agg_csr<<<(n * 32 + T - 1) / T, T>>>(ph, b2, po2, n);

    pool_kernel<<<ng, HID>>>(po2, out, n);
}

// round 15
// speedup vs baseline: 2.0374x; 1.0290x over previous
#include <cuda_runtime.h>
#include <cuda_fp16.h>
#include <cstdint>

#define MAX_NODES 100000
#define MAX_EDGES 3200000
#define MAX_GRAPHS 512
#define HID 64
#define SCAN_B 256

// Scratch (static device globals)
__device__ __align__(16) __half g_h [MAX_NODES * HID];   // h_pre = (X@W)*dis, fp16
__device__ __align__(16) float g_o1 [MAX_NODES * HID];   // layer-1 out (relu'd)
__device__ __align__(16) float g_o2 [MAX_NODES * HID];   // layer-2 out (relu'd)
__device__ __align__(16) float g_dis[MAX_NODES];         // rsqrt(deg)
__device__ int g_src   [MAX_EDGES];
__device__ int g_dst   [MAX_EDGES];
__device__ int g_ssrc  [MAX_EDGES];                      // src sorted by dst (CSR)
__device__ int g_count [MAX_NODES];                      // in-degree (no self loop)
__device__ int g_rowst [MAX_NODES];                      // CSR row start
__device__ int g_cursor[MAX_NODES];
__device__ int g_bsum  [(MAX_NODES + SCAN_B - 1) / SCAN_B];
__device__ int g_boff  [(MAX_NODES + SCAN_B - 1) / SCAN_B];
__device__ int g_batch [MAX_NODES];
__device__ unsigned g_flags[2];

// ---------------------------------------------------------------------------
// Launch 1: zero degree counters (wide grid — was a 1-block serial bottleneck).
__global__ void init_count(int n) {
    int i = blockIdx.x * blockDim.x + threadIdx.x;
    if (i < n) g_count[i] = 0;
}

// Launch 2: dtype probe only (2 KB of reads, 1 tiny block).
__global__ void probe_kernel(const unsigned* __restrict__ ei_raw, int ei_count,
                             const unsigned* __restrict__ b_raw,  int b_count)
{
    int t = threadIdx.x;                       // 256 threads, 1 block
    if (t < 2) g_flags[t] = 0u;
    __syncthreads();
    unsigned acc0 = 0, acc1 = 0;
    for (int k = t; k < 512; k += 256) {
        int w0 = ei_count - 1 - 2 * k;
        if ((w0 & 1) == 0) w0 -= 1;
        if (w0 >= 1) acc0 |= ei_raw[w0];
        int w1 = b_count - 1 - 2 * k;
        if ((w1 & 1) == 0) w1 -= 1;
        if (w1 >= 1) acc1 |= b_raw[w1];
    }
    if (acc0) atomicOr(&g_flags[0], 1u);
    if (acc1) atomicOr(&g_flags[1], 1u);
}

// Launch 3: normalize indices to int32 + in-degree histogram + batch.
__global__ void convert_kernel(const void* __restrict__ ei_raw, int e,
                               const void* __restrict__ b_raw,  int n)
{
    int i = blockIdx.x * blockDim.x + threadIdx.x;
    bool ei32 = (g_flags[0] != 0u);
    bool b32  = (g_flags[1] != 0u);
    if (i < e) {
        int s, d;
        if (ei32) {
            s = ((const int*)ei_raw)[i];
            d = ((const int*)ei_raw)[e + i];
        } else {
            s = (int)((const long long*)ei_raw)[i];
            d = (int)((const long long*)ei_raw)[e + i];
        }
        s = min(max(s, 0), n - 1);
        d = min(max(d, 0), n - 1);
        g_src[i] = s;
        g_dst[i] = d;
        atomicAdd(&g_count[d], 1);
    }
    if (i < n) {
        int g = b32 ? ((const int*)b_raw)[i]
                    : (int)((const long long*)b_raw)[i];
        g_batch[i] = min(max(g, 0), MAX_GRAPHS - 1);
    }
}

// ---------------------------------------------------------------------------
// Prefix scan -> row starts, cursors, dis.
__global__ void scan_a(int n) {
    __shared__ int s[SCAN_B];
    int i = blockIdx.x * SCAN_B + threadIdx.x;
    int v = (i < n) ? g_count[i] : 0;
    if (i < n) g_dis[i] = rsqrtf((float)v + 1.0f);
    s[threadIdx.x] = v;
    __syncthreads();
    for (int off = 1; off < SCAN_B; off <<= 1) {
        int t = (threadIdx.x >= off) ? s[threadIdx.x - off] : 0;
        __syncthreads();
        s[threadIdx.x] += t;
        __syncthreads();
    }
    if (threadIdx.x == SCAN_B - 1) g_bsum[blockIdx.x] = s[SCAN_B - 1];
}

__global__ void scan_b(int nb) {
    __shared__ int s[512];
    int t = threadIdx.x;
    int v = (t < nb) ? g_bsum[t] : 0;
    s[t] = v;
    __syncthreads();
    for (int off = 1; off < 512; off <<= 1) {
        int u = (t >= off) ? s[t - off] : 0;
        __syncthreads();
        s[t] += u;
        __syncthreads();
    }
    if (t < nb) g_boff[t] = s[t] - v;
}

__global__ void scan_c(int n) {
    __shared__ int s[SCAN_B];
    int i = blockIdx.x * SCAN_B + threadIdx.x;
    int v = (i < n) ? g_count[i] : 0;
    s[threadIdx.x] = v;
    __syncthreads();
    for (int off = 1; off < SCAN_B; off <<= 1) {
        int t = (threadIdx.x >= off) ? s[threadIdx.x - off] : 0;
        __syncthreads();
        s[threadIdx.x] += t;
        __syncthreads();
    }
    if (i < n) {
        int row = g_boff[blockIdx.x] + s[threadIdx.x] - v;
        g_rowst[i]  = row;
        g_cursor[i] = row;
    }
}

// Counting-sort scatter (CSR adjacency).
__global__ void scatter_kernel(int e) {
    int i = blockIdx.x * blockDim.x + threadIdx.x;
    if (i < e) {
        int d = g_dst[i];
        int pos = atomicAdd(&g_cursor[d], 1);
        g_ssrc[pos] = g_src[i];
    }
}

// ---------------------------------------------------------------------------
// Tensor-core GEMM: h_pre = (X @ W) * dis[r], fp16 in/out, fp32 accumulate.
// Block: 128 rows x 64 cols, 256 threads (8 warps). mma.sync m16n8k16.
template<int K>
__global__ __launch_bounds__(256)
void gcn_gemm(const float* __restrict__ X,
              const float* __restrict__ W,
              __half* __restrict__ hout,
              int n)
{
    __shared__ __align__(16) __half Xh[128][72];      // 64-col chunk + pad
    __shared__ __align__(16) __half Wt[64][K + 8];    // transposed W (n-major)

    int tid  = threadIdx.x;
    int w    = tid >> 5;
    int lane = tid & 31;
    int gr   = lane >> 2;          // 0..7
    int qp   = lane & 3;           // quad pair 0..3
    int block_row = blockIdx.x * 128;

    for (int i = tid; i < K * 64; i += 256) {
        int k = i >> 6, nn = i & 63;
        Wt[nn][k] = __float2half(W[i]);
    }

    float acc[8][4];
    #pragma unroll
    for (int nt = 0; nt < 8; ++nt)
        #pragma unroll
        for (int c = 0; c < 4; ++c) acc[nt][c] = 0.f;

    #pragma unroll
    for (int kc = 0; kc < K; kc += 64) {
        __syncthreads();
        #pragma unroll
        for (int p = 0; p < 8; ++p) {
            int idx = p * 256 + tid;
            int row = idx >> 4;
            int c4  = (idx & 15) << 2;
            int grow = block_row + row;
            float4 v = make_float4(0.f, 0.f, 0.f, 0.f);
            if (grow < n)
                v = *reinterpret_cast<const float4*>(X + (size_t)grow * K + kc + c4);
            *reinterpret_cast<__half2*>(&Xh[row][c4])     = __floats2half2_rn(v.x, v.y);
            *reinterpret_cast<__half2*>(&Xh[row][c4 + 2]) = __floats2half2_rn(v.z, v.w);
        }
        __syncthreads();

        #pragma unroll
        for (int ks = 0; ks < 4; ++ks) {
            const __half* ar0 = &Xh[w * 16 + gr][ks * 16 + qp * 2];
            const __half* ar1 = &Xh[w * 16 + gr + 8][ks * 16 + qp * 2];
            unsigned a0 = *reinterpret_cast<const unsigned*>(ar0);
            unsigned a1 = *reinterpret_cast<const unsigned*>(ar1);
            unsigned a2 = *reinterpret_cast<const unsigned*>(ar0 + 8);
            unsigned a3 = *reinterpret_cast<const unsigned*>(ar1 + 8);

            #pragma unroll
            for (int nt = 0; nt < 8; ++nt) {
                const __half* br = &Wt[nt * 8 + gr][kc + ks * 16 + qp * 2];
                unsigned b0 = *reinterpret_cast<const unsigned*>(br);
                unsigned b1 = *reinterpret_cast<const unsigned*>(br + 8);
                asm volatile(
                    "mma.sync.aligned.m16n8k16.row.col.f32.f16.f16.f32 "
                    "{%0,%1,%2,%3}, {%4,%5,%6,%7}, {%8,%9}, {%0,%1,%2,%3};"
                    : "+f"(acc[nt][0]), "+f"(acc[nt][1]),
                      "+f"(acc[nt][2]), "+f"(acc[nt][3])
                    : "r"(a0), "r"(a1), "r"(a2), "r"(a3), "r"(b0), "r"(b1));
            }
        }
    }

    int r0 = block_row + w * 16 + gr;
    int r1 = r0 + 8;
    float ds0 = (r0 < n) ? g_dis[r0] : 0.f;
    float ds1 = (r1 < n) ? g_dis[r1] : 0.f;
    #pragma unroll
    for (int nt = 0; nt < 8; ++nt) {
        int c = nt * 8 + qp * 2;
        if (r0 < n)
            *reinterpret_cast<__half2*>(hout + (size_t)r0 * HID + c) =
                __floats2half2_rn(acc[nt][0] * ds0, acc[nt][1] * ds0);
        if (r1 < n)
            *reinterpret_cast<__half2*>(hout + (size_t)r1 * HID + c) =
                __floats2half2_rn(acc[nt][2] * ds1, acc[nt][3] * ds1);
    }
}

// ---------------------------------------------------------------------------
// CSR aggregation, fp16 gather / fp32 accumulate, paired edges with 4
// gathers in flight (8 edges/iter): lanes 0-15 even edge, 16-31 odd edge.
//   out[d] = relu( (h[d] + sum_{s in row(d)} h[s]) * dis[d] + b )
__global__ void agg_csr(const __half* __restrict__ h,
                        const float* __restrict__ bias,
                        float* __restrict__ out,
                        int n)
{
    int warp = (blockIdx.x * blockDim.x + threadIdx.x) >> 5;
    int lane = threadIdx.x & 31;
    if (warp >= n) return;

    const uint2* hp = reinterpret_cast<const uint2*>(h);   // node row = 16 uint2
    int half = lane >> 4;
    int ch   = lane & 15;

    float4 acc = make_float4(0.f, 0.f, 0.f, 0.f);
#define ADDV(v) do {                                                   \
        __half2 _h0 = *reinterpret_cast<const __half2*>(&(v).x);      \
        __half2 _h1 = *reinterpret_cast<const __half2*>(&(v).y);      \
        float2 _f0 = __half22float2(_h0), _f1 = __half22float2(_h1);  \
        acc.x += _f0.x; acc.y += _f0.y; acc.z += _f1.x; acc.w += _f1.y; \
    } while (0)

    if (half == 0) { uint2 sv = hp[(size_t)warp * 16 + ch]; ADDV(sv); }

    int beg = g_rowst[warp];
    int end = beg + g_count[warp];

    int j = beg;
    for (; j + 7 < end; j += 8) {             // 4 paired gathers in flight
        int s0 = g_ssrc[j + half];
        int s1 = g_ssrc[j + 2 + half];
        int s2 = g_ssrc[j + 4 + half];
        int s3 = g_ssrc[j + 6 + half];
        uint2 v0 = hp[(size_t)s0 * 16 + ch];
        uint2 v1 = hp[(size_t)s1 * 16 + ch];
        uint2 v2 = hp[(size_t)s2 * 16 + ch];
        uint2 v3 = hp[(size_t)s3 * 16 + ch];
        ADDV(v0); ADDV(v1); ADDV(v2); ADDV(v3);
    }
    for (; j + 3 < end; j += 4) {
        int s0 = g_ssrc[j + half];
        int s1 = g_ssrc[j + 2 + half];
        uint2 v0 = hp[(size_t)s0 * 16 + ch];
        uint2 v1 = hp[(size_t)s1 * 16 + ch];
        ADDV(v0); ADDV(v1);
    }
    for (; j < end; j += 2) {
        int idx = j + half;
        if (idx < end) {
            int s = g_ssrc[idx];
            uint2 v = hp[(size_t)s * 16 + ch];
            ADDV(v);
        }
    }
#undef ADDV

    acc.x += __shfl_xor_sync(0xffffffffu, acc.x, 16);
    acc.y += __shfl_xor_sync(0xffffffffu, acc.y, 16);
    acc.z += __shfl_xor_sync(0xffffffffu, acc.z, 16);
    acc.w += __shfl_xor_sync(0xffffffffu, acc.w, 16);

    if (half == 0) {
        float ds = g_dis[warp];
        float4 b = __ldg(&reinterpret_cast<const float4*>(bias)[ch]);
        float4 o;
        o.x = fmaxf(fmaf(acc.x, ds, b.x), 0.f);
        o.y = fmaxf(fmaf(acc.y, ds, b.y), 0.f);
        o.z = fmaxf(fmaf(acc.z, ds, b.z), 0.f);
        o.w = fmaxf(fmaf(acc.w, ds, b.w), 0.f);
        reinterpret_cast<float4*>(out)[(size_t)warp * 16 + ch] = o;
    }
}

// ---------------------------------------------------------------------------
// Pool over sorted batch: one block per graph, binary-searched node range.
__global__ void pool_kernel(const float* __restrict__ o2,
                            float* __restrict__ out,
                            int n)
{
    int g = blockIdx.x;
    int c = threadIdx.x;                       // 64 threads = 64 channels

    int lo = 0, hi = n;
    while (lo < hi) { int m = (lo + hi) >> 1; if (g_batch[m] < g) lo = m + 1; else hi = m; }
    int start = lo;
    hi = n;
    while (lo < hi) { int m = (lo + hi) >> 1; if (g_batch[m] < g + 1) lo = m + 1; else hi = m; }
    int end = lo;

    float sum = 0.f;
    int i = start;
    for (; i + 3 < end; i += 4) {
        float a0 = o2[(size_t)i * HID + c];
        float a1 = o2[(size_t)(i + 1) * HID + c];
        float a2 = o2[(size_t)(i + 2) * HID + c];
        float a3 = o2[(size_t)(i + 3) * HID + c];
        sum += (a0 + a1) + (a2 + a3);
    }
    for (; i < end; ++i) sum += o2[(size_t)i * HID + c];

    out[g * HID + c] = sum / (float)max(end - start, 1);
}

// ---------------------------------------------------------------------------
extern "C" void kernel_launch(void* const* d_in, const int* in_sizes, int n_in,
                              void* d_out, int out_size)
{
    const float* x  = nullptr;
    const void  *ei = nullptr, *bt = nullptr;
    const float *W1 = nullptr, *W2 = nullptr, *b1 = nullptr, *b2 = nullptr;
    int n = 0, e = 0;

    long long maxsz = 0;
    for (int i = 0; i < n_in; ++i) if (in_sizes[i] > maxsz) maxsz = in_sizes[i];
    for (int i = 0; i < n_in; ++i)
        if (in_sizes[i] == maxsz && !x) { x = (const float*)d_in[i]; n = (int)(maxsz / 128); }
    for (int i = 0; i < n_in; ++i) {
        long long sz = in_sizes[i];
        const void* p = d_in[i];
        if (p == (const void*)x) continue;
        if (sz == (long long)n)      { bt = p; }
        else if (sz > (long long)n)  { ei = p; e = (int)(sz / 2); }
        else if (sz == 128 * 64)     { W1 = (const float*)p; }
        else if (sz == 64 * 64)      { W2 = (const float*)p; }
        else if (sz == 64)           { if (!b1) b1 = (const float*)p; else b2 = (const float*)p; }
    }

    float* out = (float*)d_out;
    const int ng = out_size / HID;

    __half* ph;
    float *po1, *po2;
    cudaGetSymbolAddress((void**)&ph,  g_h);
    cudaGetSymbolAddress((void**)&po1, g_o1);
    cudaGetSymbolAddress((void**)&po2, g_o2);

    const int T = 256;
    const int mx = (e > n ? e : n);
    const int nb = (n + SCAN_B - 1) / SCAN_B;
    const int gb = (n + 127) / 128;            // GEMM blocks (128 rows each)

    init_count    <<<(n + T - 1) / T, T>>>(n);
    probe_kernel  <<<1, 256>>>((const unsigned*)ei, 2 * e, (const unsigned*)bt, n);
    convert_kernel<<<(mx + T - 1) / T, T>>>(ei, e, bt, n);
    scan_a        <<<nb, SCAN_B>>>(n);                          // writes g_dis

    gcn_gemm<128><<<gb, 256>>>(x, W1, ph, n);                   // after scan_a (reads g_dis)

    scan_b<<<1, 512>>>(nb);
    scan_c<<<nb, SCAN_B>>>(n);
    scatter_kernel<<<(e + T - 1) / T, T>>>(e);

    agg_csr<<<(n * 32 + T - 1) / T, T>>>(ph, b1, po1, n);

    gcn_gemm<64><<<gb, 256>>>(po1, W2, ph, n);
    agg_csr<<<(n * 32 + T - 1) / T, T>>>(ph, b2, po2, n);

    pool_kernel<<<ng, HID>>>(po2, out, n);
}

// round 16
// speedup vs baseline: 2.0797x; 1.0208x over previous
#include <cuda_runtime.h>
#include <cuda_fp16.h>
#include <cstdint>

#define MAX_NODES 100000
#define MAX_EDGES 3200000
#define MAX_GRAPHS 512
#define HID 64
#define SCAN_B 256

// Scratch (static device globals)
__device__ __align__(16) __half g_h [MAX_NODES * HID];   // h_pre = (X@W)*dis, fp16
__device__ __align__(16) __half g_o1[MAX_NODES * HID];   // layer-1 out (relu'd), fp16
__device__ __align__(16) __half g_o2[MAX_NODES * HID];   // layer-2 out (relu'd), fp16
__device__ __align__(16) float g_dis[MAX_NODES];         // rsqrt(deg)
__device__ int g_ssrc  [MAX_EDGES];                      // src sorted by dst (CSR)
__device__ int g_count [MAX_NODES];                      // in-degree (no self loop)
__device__ int g_rowst [MAX_NODES];                      // CSR row start
__device__ int g_cursor[MAX_NODES];
__device__ int g_bsum  [(MAX_NODES + SCAN_B - 1) / SCAN_B];
__device__ int g_boff  [(MAX_NODES + SCAN_B - 1) / SCAN_B];
__device__ int g_batch [MAX_NODES];
__device__ unsigned g_flags[2];

// ---------------------------------------------------------------------------
// Launch 1: zero degree counters.
__global__ void init_count(int n) {
    int i = blockIdx.x * blockDim.x + threadIdx.x;
    if (i < n) g_count[i] = 0;
}

// Launch 2: dtype probe (int64 data has zero high words; int32 tails nonzero).
__global__ void probe_kernel(const unsigned* __restrict__ ei_raw, int ei_count,
                             const unsigned* __restrict__ b_raw,  int b_count)
{
    int t = threadIdx.x;                       // 256 threads, 1 block
    if (t < 2) g_flags[t] = 0u;
    __syncthreads();
    unsigned acc0 = 0, acc1 = 0;
    for (int k = t; k < 512; k += 256) {
        int w0 = ei_count - 1 - 2 * k;
        if ((w0 & 1) == 0) w0 -= 1;
        if (w0 >= 1) acc0 |= ei_raw[w0];
        int w1 = b_count - 1 - 2 * k;
        if ((w1 & 1) == 0) w1 -= 1;
        if (w1 >= 1) acc1 |= b_raw[w1];
    }
    if (acc0) atomicOr(&g_flags[0], 1u);
    if (acc1) atomicOr(&g_flags[1], 1u);
}

// Launch 3: in-degree histogram from raw dst half + batch decode.
// (No index scratch writes — scatter re-decodes the raw edge list itself.)
__global__ void convert_kernel(const void* __restrict__ ei_raw, int e,
                               const void* __restrict__ b_raw,  int n)
{
    int i = blockIdx.x * blockDim.x + threadIdx.x;
    bool ei32 = (g_flags[0] != 0u);
    bool b32  = (g_flags[1] != 0u);
    if (i < e) {
        int d = ei32 ? ((const int*)ei_raw)[e + i]
                     : (int)((const long long*)ei_raw)[e + i];
        d = min(max(d, 0), n - 1);
        atomicAdd(&g_count[d], 1);
    }
    if (i < n) {
        int g = b32 ? ((const int*)b_raw)[i]
                    : (int)((const long long*)b_raw)[i];
        g_batch[i] = min(max(g, 0), MAX_GRAPHS - 1);
    }
}

// ---------------------------------------------------------------------------
// Prefix scan -> row starts, cursors, dis.
__global__ void scan_a(int n) {
    __shared__ int s[SCAN_B];
    int i = blockIdx.x * SCAN_B + threadIdx.x;
    int v = (i < n) ? g_count[i] : 0;
    if (i < n) g_dis[i] = rsqrtf((float)v + 1.0f);
    s[threadIdx.x] = v;
    __syncthreads();
    for (int off = 1; off < SCAN_B; off <<= 1) {
        int t = (threadIdx.x >= off) ? s[threadIdx.x - off] : 0;
        __syncthreads();
        s[threadIdx.x] += t;
        __syncthreads();
    }
    if (threadIdx.x == SCAN_B - 1) g_bsum[blockIdx.x] = s[SCAN_B - 1];
}

__global__ void scan_b(int nb) {
    __shared__ int s[512];
    int t = threadIdx.x;
    int v = (t < nb) ? g_bsum[t] : 0;
    s[t] = v;
    __syncthreads();
    for (int off = 1; off < 512; off <<= 1) {
        int u = (t >= off) ? s[t - off] : 0;
        __syncthreads();
        s[t] += u;
        __syncthreads();
    }
    if (t < nb) g_boff[t] = s[t] - v;
}

__global__ void scan_c(int n) {
    __shared__ int s[SCAN_B];
    int i = blockIdx.x * SCAN_B + threadIdx.x;
    int v = (i < n) ? g_count[i] : 0;
    s[threadIdx.x] = v;
    __syncthreads();
    for (int off = 1; off < SCAN_B; off <<= 1) {
        int t = (threadIdx.x >= off) ? s[threadIdx.x - off] : 0;
        __syncthreads();
        s[threadIdx.x] += t;
        __syncthreads();
    }
    if (i < n) {
        int row = g_boff[blockIdx.x] + s[threadIdx.x] - v;
        g_rowst[i]  = row;
        g_cursor[i] = row;
    }
}

// Counting-sort scatter: decodes the raw edge list directly.
__global__ void scatter_kernel(const void* __restrict__ ei_raw, int e, int n) {
    int i = blockIdx.x * blockDim.x + threadIdx.x;
    if (i >= e) return;
    bool ei32 = (g_flags[0] != 0u);
    int s, d;
    if (ei32) {
        s = ((const int*)ei_raw)[i];
        d = ((const int*)ei_raw)[e + i];
    } else {
        s = (int)((const long long*)ei_raw)[i];
        d = (int)((const long long*)ei_raw)[e + i];
    }
    s = min(max(s, 0), n - 1);
    d = min(max(d, 0), n - 1);
    int pos = atomicAdd(&g_cursor[d], 1);
    g_ssrc[pos] = s;
}

// ---------------------------------------------------------------------------
// Tensor-core GEMM: h_pre = (X @ W) * dis[r], fp16 compute, fp32 accumulate.
// INHALF: X is fp16 (layer 2 reads o1 directly). Output fp16.
// Block: 128 rows x 64 cols, 256 threads (8 warps). mma.sync m16n8k16.
template<int K, bool INHALF>
__global__ __launch_bounds__(256)
void gcn_gemm(const void* __restrict__ X,
              const float* __restrict__ W,
              __half* __restrict__ hout,
              int n)
{
    __shared__ __align__(16) __half Xh[128][72];      // 64-col chunk + pad
    __shared__ __align__(16) __half Wt[64][K + 8];    // transposed W (n-major)

    int tid  = threadIdx.x;
    int w    = tid >> 5;
    int lane = tid & 31;
    int gr   = lane >> 2;          // 0..7
    int qp   = lane & 3;           // quad pair 0..3
    int block_row = blockIdx.x * 128;

    for (int i = tid; i < K * 64; i += 256) {
        int k = i >> 6, nn = i & 63;
        Wt[nn][k] = __float2half(W[i]);
    }

    float acc[8][4];
    #pragma unroll
    for (int nt = 0; nt < 8; ++nt)
        #pragma unroll
        for (int c = 0; c < 4; ++c) acc[nt][c] = 0.f;

    #pragma unroll
    for (int kc = 0; kc < K; kc += 64) {
        __syncthreads();
        #pragma unroll
        for (int p = 0; p < 8; ++p) {
            int idx = p * 256 + tid;
            int row = idx >> 4;
            int c4  = (idx & 15) << 2;
            int grow = block_row + row;
            if (INHALF) {
                uint2 v = make_uint2(0u, 0u);
                if (grow < n)
                    v = *reinterpret_cast<const uint2*>(
                        (const __half*)X + (size_t)grow * K + kc + c4);
                *reinterpret_cast<uint2*>(&Xh[row][c4]) = v;
            } else {
                float4 v = make_float4(0.f, 0.f, 0.f, 0.f);
                if (grow < n)
                    v = *reinterpret_cast<const float4*>(
                        (const float*)X + (size_t)grow * K + kc + c4);
                *reinterpret_cast<__half2*>(&Xh[row][c4])     = __floats2half2_rn(v.x, v.y);
                *reinterpret_cast<__half2*>(&Xh[row][c4 + 2]) = __floats2half2_rn(v.z, v.w);
            }
        }
        __syncthreads();

        #pragma unroll
        for (int ks = 0; ks < 4; ++ks) {
            const __half* ar0 = &Xh[w * 16 + gr][ks * 16 + qp * 2];
            const __half* ar1 = &Xh[w * 16 + gr + 8][ks * 16 + qp * 2];
            unsigned a0 = *reinterpret_cast<const unsigned*>(ar0);
            unsigned a1 = *reinterpret_cast<const unsigned*>(ar1);
            unsigned a2 = *reinterpret_cast<const unsigned*>(ar0 + 8);
            unsigned a3 = *reinterpret_cast<const unsigned*>(ar1 + 8);

            #pragma unroll
            for (int nt = 0; nt < 8; ++nt) {
                const __half* br = &Wt[nt * 8 + gr][kc + ks * 16 + qp * 2];
                unsigned b0 = *reinterpret_cast<const unsigned*>(br);
                unsigned b1 = *reinterpret_cast<const unsigned*>(br + 8);
                asm volatile(
                    "mma.sync.aligned.m16n8k16.row.col.f32.f16.f16.f32 "
                    "{%0,%1,%2,%3}, {%4,%5,%6,%7}, {%8,%9}, {%0,%1,%2,%3};"
                    : "+f"(acc[nt][0]), "+f"(acc[nt][1]),
                      "+f"(acc[nt][2]), "+f"(acc[nt][3])
                    : "r"(a0), "r"(a1), "r"(a2), "r"(a3), "r"(b0), "r"(b1));
            }
        }
    }

    int r0 = block_row + w * 16 + gr;
    int r1 = r0 + 8;
    float ds0 = (r0 < n) ? g_dis[r0] : 0.f;
    float ds1 = (r1 < n) ? g_dis[r1] : 0.f;
    #pragma unroll
    for (int nt = 0; nt < 8; ++nt) {
        int c = nt * 8 + qp * 2;
        if (r0 < n)
            *reinterpret_cast<__half2*>(hout + (size_t)r0 * HID + c) =
                __floats2half2_rn(acc[nt][0] * ds0, acc[nt][1] * ds0);
        if (r1 < n)
            *reinterpret_cast<__half2*>(hout + (size_t)r1 * HID + c) =
                __floats2half2_rn(acc[nt][2] * ds1, acc[nt][3] * ds1);
    }
}

// ---------------------------------------------------------------------------
// CSR aggregation, fp16 gather / fp32 accumulate, paired edges with 4
// gathers in flight (8 edges/iter). Output fp16.
//   out[d] = relu( (h[d] + sum_{s in row(d)} h[s]) * dis[d] + b )
__global__ void agg_csr(const __half* __restrict__ h,
                        const float* __restrict__ bias,
                        __half* __restrict__ out,
                        int n)
{
    int warp = (blockIdx.x * blockDim.x + threadIdx.x) >> 5;
    int lane = threadIdx.x & 31;
    if (warp >= n) return;

    const uint2* hp = reinterpret_cast<const uint2*>(h);   // node row = 16 uint2
    int half = lane >> 4;
    int ch   = lane & 15;

    float4 acc = make_float4(0.f, 0.f, 0.f, 0.f);
#define ADDV(v) do {                                                   \
        __half2 _h0 = *reinterpret_cast<const __half2*>(&(v).x);      \
        __half2 _h1 = *reinterpret_cast<const __half2*>(&(v).y);      \
        float2 _f0 = __half22float2(_h0), _f1 = __half22float2(_h1);  \
        acc.x += _f0.x; acc.y += _f0.y; acc.z += _f1.x; acc.w += _f1.y; \
    } while (0)

    if (half == 0) { uint2 sv = hp[(size_t)warp * 16 + ch]; ADDV(sv); }

    int beg = g_rowst[warp];
    int end = beg + g_count[warp];

    int j = beg;
    for (; j + 7 < end; j += 8) {             // 4 paired gathers in flight
        int s0 = g_ssrc[j + half];
        int s1 = g_ssrc[j + 2 + half];
        int s2 = g_ssrc[j + 4 + half];
        int s3 = g_ssrc[j + 6 + half];
        uint2 v0 = hp[(size_t)s0 * 16 + ch];
        uint2 v1 = hp[(size_t)s1 * 16 + ch];
        uint2 v2 = hp[(size_t)s2 * 16 + ch];
        uint2 v3 = hp[(size_t)s3 * 16 + ch];
        ADDV(v0); ADDV(v1); ADDV(v2); ADDV(v3);
    }
    for (; j + 3 < end; j += 4) {
        int s0 = g_ssrc[j + half];
        int s1 = g_ssrc[j + 2 + half];
        uint2 v0 = hp[(size_t)s0 * 16 + ch];
        uint2 v1 = hp[(size_t)s1 * 16 + ch];
        ADDV(v0); ADDV(v1);
    }
    for (; j < end; j += 2) {
        int idx = j + half;
        if (idx < end) {
            int s = g_ssrc[idx];
            uint2 v = hp[(size_t)s * 16 + ch];
            ADDV(v);
        }
    }
#undef ADDV

    acc.x += __shfl_xor_sync(0xffffffffu, acc.x, 16);
    acc.y += __shfl_xor_sync(0xffffffffu, acc.y, 16);
    acc.z += __shfl_xor_sync(0xffffffffu, acc.z, 16);
    acc.w += __shfl_xor_sync(0xffffffffu, acc.w, 16);

    if (half == 0) {
        float ds = g_dis[warp];
        float4 b = __ldg(&reinterpret_cast<const float4*>(bias)[ch]);
        __half2 h0 = __floats2half2_rn(fmaxf(fmaf(acc.x, ds, b.x), 0.f),
                                       fmaxf(fmaf(acc.y, ds, b.y), 0.f));
        __half2 h1 = __floats2half2_rn(fmaxf(fmaf(acc.z, ds, b.z), 0.f),
                                       fmaxf(fmaf(acc.w, ds, b.w), 0.f));
        uint2 st;
        st.x = *reinterpret_cast<unsigned*>(&h0);
        st.y = *reinterpret_cast<unsigned*>(&h1);
        reinterpret_cast<uint2*>(out)[(size_t)warp * 16 + ch] = st;
    }
}

// ---------------------------------------------------------------------------
// Pool over sorted batch (fp16 input, fp32 output): one block per graph.
__global__ void pool_kernel(const __half* __restrict__ o2,
                            float* __restrict__ out,
                            int n)
{
    int g = blockIdx.x;
    int c = threadIdx.x;                       // 64 threads = 64 channels

    int lo = 0, hi = n;
    while (lo < hi) { int m = (lo + hi) >> 1; if (g_batch[m] < g) lo = m + 1; else hi = m; }
    int start = lo;
    hi = n;
    while (lo < hi) { int m = (lo + hi) >> 1; if (g_batch[m] < g + 1) lo = m + 1; else hi = m; }
    int end = lo;

    float sum = 0.f;
    int i = start;
    for (; i + 3 < end; i += 4) {
        float a0 = __half2float(o2[(size_t)i * HID + c]);
        float a1 = __half2float(o2[(size_t)(i + 1) * HID + c]);
        float a2 = __half2float(o2[(size_t)(i + 2) * HID + c]);
        float a3 = __half2float(o2[(size_t)(i + 3) * HID + c]);
        sum += (a0 + a1) + (a2 + a3);
    }
    for (; i < end; ++i) sum += __half2float(o2[(size_t)i * HID + c]);

    out[g * HID + c] = sum / (float)max(end - start, 1);
}

// ---------------------------------------------------------------------------
extern "C" void kernel_launch(void* const* d_in, const int* in_sizes, int n_in,
                              void* d_out, int out_size)
{
    const float* x  = nullptr;
    const void  *ei = nullptr, *bt = nullptr;
    const float *W1 = nullptr, *W2 = nullptr, *b1 = nullptr, *b2 = nullptr;
    int n = 0, e = 0;

    long long maxsz = 0;
    for (int i = 0; i < n_in; ++i) if (in_sizes[i] > maxsz) maxsz = in_sizes[i];
    for (int i = 0; i < n_in; ++i)
        if (in_sizes[i] == maxsz && !x) { x = (const float*)d_in[i]; n = (int)(maxsz / 128); }
    for (int i = 0; i < n_in; ++i) {
        long long sz = in_sizes[i];
        const void* p = d_in[i];
        if (p == (const void*)x) continue;
        if (sz == (long long)n)      { bt = p; }
        else if (sz > (long long)n)  { ei = p; e = (int)(sz / 2); }
        else if (sz == 128 * 64)     { W1 = (const float*)p; }
        else if (sz == 64 * 64)      { W2 = (const float*)p; }
        else if (sz == 64)           { if (!b1) b1 = (const float*)p; else b2 = (const float*)p; }
    }

    float* out = (float*)d_out;
    const int ng = out_size / HID;

    __half *ph, *po1, *po2;
    cudaGetSymbolAddress((void**)&ph,  g_h);
    cudaGetSymbolAddress((void**)&po1, g_o1);
    cudaGetSymbolAddress((void**)&po2, g_o2);

    const int T = 256;
    const int mx = (e > n ? e : n);
    const int nb = (n + SCAN_B - 1) / SCAN_B;
    const int gb = (n + 127) / 128;            // GEMM blocks (128 rows each)

    init_count    <<<(n + T - 1) / T, T>>>(n);
    probe_kernel  <<<1, 256>>>((const unsigned*)ei, 2 * e, (const unsigned*)bt, n);
    convert_kernel<<<(mx + T - 1) / T, T>>>(ei, e, bt, n);
    scan_a        <<<nb, SCAN_B>>>(n);                          // writes g_dis

    gcn_gemm<128, false><<<gb, 256>>>(x, W1, ph, n);            // reads g_dis

    scan_b<<<1, 512>>>(nb);
    scan_c<<<nb, SCAN_B>>>(n);
    scatter_kernel<<<(e + T - 1) / T, T>>>(ei, e, n);

    agg_csr<<<(n * 32 + T - 1) / T, T>>>(ph, b1, po1, n);

    gcn_gemm<64, true><<<gb, 256>>>(po1, W2, ph, n);
    agg_csr<<<(n * 32 + T - 1) / T, T>>>(ph, b2, po2, n);

    pool_kernel<<<ng, HID>>>(po2, out, n);
}

// round 17
// speedup vs baseline: 2.1197x; 1.0192x over previous
#include <cuda_runtime.h>
#include <cuda_fp16.h>
#include <cstdint>

#define MAX_NODES 100000
#define MAX_EDGES 3200000
#define MAX_GRAPHS 512
#define HID 64
#define SCAN_B 256

// Scratch (static device globals)
__device__ __align__(16) __half g_h [MAX_NODES * HID];   // h_pre = (X@W)*dis, fp16
__device__ __align__(16) __half g_o1[MAX_NODES * HID];   // layer-1 out (relu'd), fp16
__device__ __align__(16) __half g_o2[MAX_NODES * HID];   // layer-2 out (relu'd), fp16
__device__ __align__(16) float g_dis[MAX_NODES];         // rsqrt(deg)
__device__ int g_ssrc  [MAX_EDGES];                      // src sorted by dst (CSR)
__device__ int g_count [MAX_NODES];                      // in-degree (no self loop)
__device__ int g_rowst [MAX_NODES];                      // CSR row start
__device__ int g_cursor[MAX_NODES];
__device__ int g_bsum  [(MAX_NODES + SCAN_B - 1) / SCAN_B];
__device__ int g_batch [MAX_NODES];
__device__ unsigned g_flags[2];

// ---------------------------------------------------------------------------
// Launch 1: zero degree counters (all blocks) + dtype probe (block 0 only).
// int64 data has zero high words; int32 tails are nonzero for this dataset.
__global__ void probe_init(const unsigned* __restrict__ ei_raw, int ei_count,
                           const unsigned* __restrict__ b_raw,  int b_count,
                           int n)
{
    int i = blockIdx.x * blockDim.x + threadIdx.x;
    if (i < n) g_count[i] = 0;

    if (blockIdx.x == 0) {
        int t = threadIdx.x;
        if (t < 2) g_flags[t] = 0u;
        __syncthreads();
        unsigned acc0 = 0, acc1 = 0;
        for (int k = t; k < 512; k += blockDim.x) {
            int w0 = ei_count - 1 - 2 * k;
            if ((w0 & 1) == 0) w0 -= 1;
            if (w0 >= 1) acc0 |= ei_raw[w0];
            int w1 = b_count - 1 - 2 * k;
            if ((w1 & 1) == 0) w1 -= 1;
            if (w1 >= 1) acc1 |= b_raw[w1];
        }
        if (acc0) atomicOr(&g_flags[0], 1u);
        if (acc1) atomicOr(&g_flags[1], 1u);
    }
}

// ---------------------------------------------------------------------------
// Launch 2: in-degree histogram from raw dst half + batch decode.
// Vectorized: one thread = 2 edges (longlong2 / int2) when e is even.
__global__ void convert_kernel(const void* __restrict__ ei_raw, int e,
                               const void* __restrict__ b_raw,  int n)
{
    int i = blockIdx.x * blockDim.x + threadIdx.x;
    bool ei32 = (g_flags[0] != 0u);
    bool b32  = (g_flags[1] != 0u);
    bool vec  = ((e & 1) == 0);

    if (vec) {
        int p = i;                                // pair index
        if (p * 2 < e) {
            int d0, d1;
            if (ei32) {
                int2 v = *reinterpret_cast<const int2*>((const int*)ei_raw + e + p * 2);
                d0 = v.x; d1 = v.y;
            } else {
                longlong2 v = *reinterpret_cast<const longlong2*>(
                    (const long long*)ei_raw + e + p * 2);
                d0 = (int)v.x; d1 = (int)v.y;
            }
            d0 = min(max(d0, 0), n - 1);
            d1 = min(max(d1, 0), n - 1);
            atomicAdd(&g_count[d0], 1);
            atomicAdd(&g_count[d1], 1);
        }
    } else {
        if (i < e) {
            int d = ei32 ? ((const int*)ei_raw)[e + i]
                         : (int)((const long long*)ei_raw)[e + i];
            d = min(max(d, 0), n - 1);
            atomicAdd(&g_count[d], 1);
        }
    }

    if (i < n) {
        int g = b32 ? ((const int*)b_raw)[i]
                    : (int)((const long long*)b_raw)[i];
        g_batch[i] = min(max(g, 0), MAX_GRAPHS - 1);
    }
}

// ---------------------------------------------------------------------------
// Launch 3: per-block scan sums + dis = rsqrt(deg+1).
__global__ void scan_a(int n) {
    __shared__ int s[SCAN_B];
    int i = blockIdx.x * SCAN_B + threadIdx.x;
    int v = (i < n) ? g_count[i] : 0;
    if (i < n) g_dis[i] = rsqrtf((float)v + 1.0f);
    s[threadIdx.x] = v;
    __syncthreads();
    for (int off = 1; off < SCAN_B; off <<= 1) {
        int t = (threadIdx.x >= off) ? s[threadIdx.x - off] : 0;
        __syncthreads();
        s[threadIdx.x] += t;
        __syncthreads();
    }
    if (threadIdx.x == SCAN_B - 1) g_bsum[blockIdx.x] = s[SCAN_B - 1];
}

// Launch 5: final row starts + cursors. Each block computes its own prefix
// over g_bsum (replaces the old scan_b launch).
__global__ void scan_c(int n) {
    __shared__ int s[SCAN_B];
    __shared__ int base_sh;

    // Block offset = sum of g_bsum[0 .. blockIdx.x)
    int partial = 0;
    for (int k = threadIdx.x; k < blockIdx.x; k += SCAN_B)
        partial += g_bsum[k];
    s[threadIdx.x] = partial;
    __syncthreads();
    for (int off = SCAN_B / 2; off > 0; off >>= 1) {
        if (threadIdx.x < off) s[threadIdx.x] += s[threadIdx.x + off];
        __syncthreads();
    }
    if (threadIdx.x == 0) base_sh = s[0];
    __syncthreads();
    int base = base_sh;
    __syncthreads();                       // s[] reused below

    int i = blockIdx.x * SCAN_B + threadIdx.x;
    int v = (i < n) ? g_count[i] : 0;
    s[threadIdx.x] = v;
    __syncthreads();
    for (int off = 1; off < SCAN_B; off <<= 1) {
        int t = (threadIdx.x >= off) ? s[threadIdx.x - off] : 0;
        __syncthreads();
        s[threadIdx.x] += t;
        __syncthreads();
    }
    if (i < n) {
        int row = base + s[threadIdx.x] - v;   // exclusive
        g_rowst[i]  = row;
        g_cursor[i] = row;
    }
}

// Launch 6: counting-sort scatter, decoding the raw edge list directly.
// Vectorized: one thread = 2 edges when e is even.
__global__ void scatter_kernel(const void* __restrict__ ei_raw, int e, int n) {
    int i = blockIdx.x * blockDim.x + threadIdx.x;
    bool ei32 = (g_flags[0] != 0u);
    bool vec  = ((e & 1) == 0);

    if (vec) {
        int p = i;
        if (p * 2 >= e) return;
        int s0, s1, d0, d1;
        if (ei32) {
            int2 sv = *reinterpret_cast<const int2*>((const int*)ei_raw + p * 2);
            int2 dv = *reinterpret_cast<const int2*>((const int*)ei_raw + e + p * 2);
            s0 = sv.x; s1 = sv.y; d0 = dv.x; d1 = dv.y;
        } else {
            longlong2 sv = *reinterpret_cast<const longlong2*>(
                (const long long*)ei_raw + p * 2);
            longlong2 dv = *reinterpret_cast<const longlong2*>(
                (const long long*)ei_raw + e + p * 2);
            s0 = (int)sv.x; s1 = (int)sv.y; d0 = (int)dv.x; d1 = (int)dv.y;
        }
        s0 = min(max(s0, 0), n - 1); d0 = min(max(d0, 0), n - 1);
        s1 = min(max(s1, 0), n - 1); d1 = min(max(d1, 0), n - 1);
        int p0 = atomicAdd(&g_cursor[d0], 1);
        g_ssrc[p0] = s0;
        int p1 = atomicAdd(&g_cursor[d1], 1);
        g_ssrc[p1] = s1;
    } else {
        if (i >= e) return;
        int s, d;
        if (ei32) {
            s = ((const int*)ei_raw)[i];
            d = ((const int*)ei_raw)[e + i];
        } else {
            s = (int)((const long long*)ei_raw)[i];
            d = (int)((const long long*)ei_raw)[e + i];
        }
        s = min(max(s, 0), n - 1);
        d = min(max(d, 0), n - 1);
        int pos = atomicAdd(&g_cursor[d], 1);
        g_ssrc[pos] = s;
    }
}

// ---------------------------------------------------------------------------
// Tensor-core GEMM: h_pre = (X @ W) * dis[r], fp16 compute, fp32 accumulate.
// INHALF: X is fp16 (layer 2 reads o1 directly). Output fp16.
// Block: 128 rows x 64 cols, 256 threads (8 warps). mma.sync m16n8k16.
template<int K, bool INHALF>
__global__ __launch_bounds__(256)
void gcn_gemm(const void* __restrict__ X,
              const float* __restrict__ W,
              __half* __restrict__ hout,
              int n)
{
    __shared__ __align__(16) __half Xh[128][72];      // 64-col chunk + pad
    __shared__ __align__(16) __half Wt[64][K + 8];    // transposed W (n-major)

    int tid  = threadIdx.x;
    int w    = tid >> 5;
    int lane = tid & 31;
    int gr   = lane >> 2;          // 0..7
    int qp   = lane & 3;           // quad pair 0..3
    int block_row = blockIdx.x * 128;

    for (int i = tid; i < K * 64; i += 256) {
        int k = i >> 6, nn = i & 63;
        Wt[nn][k] = __float2half(W[i]);
    }

    float acc[8][4];
    #pragma unroll
    for (int nt = 0; nt < 8; ++nt)
        #pragma unroll
        for (int c = 0; c < 4; ++c) acc[nt][c] = 0.f;

    #pragma unroll
    for (int kc = 0; kc < K; kc += 64) {
        __syncthreads();
        #pragma unroll
        for (int p = 0; p < 8; ++p) {
            int idx = p * 256 + tid;
            int row = idx >> 4;
            int c4  = (idx & 15) << 2;
            int grow = block_row + row;
            if (INHALF) {
                uint2 v = make_uint2(0u, 0u);
                if (grow < n)
                    v = *reinterpret_cast<const uint2*>(
                        (const __half*)X + (size_t)grow * K + kc + c4);
                *reinterpret_cast<uint2*>(&Xh[row][c4]) = v;
            } else {
                float4 v = make_float4(0.f, 0.f, 0.f, 0.f);
                if (grow < n)
                    v = *reinterpret_cast<const float4*>(
                        (const float*)X + (size_t)grow * K + kc + c4);
                *reinterpret_cast<__half2*>(&Xh[row][c4])     = __floats2half2_rn(v.x, v.y);
                *reinterpret_cast<__half2*>(&Xh[row][c4 + 2]) = __floats2half2_rn(v.z, v.w);
            }
        }
        __syncthreads();

        #pragma unroll
        for (int ks = 0; ks < 4; ++ks) {
            const __half* ar0 = &Xh[w * 16 + gr][ks * 16 + qp * 2];
            const __half* ar1 = &Xh[w * 16 + gr + 8][ks * 16 + qp * 2];
            unsigned a0 = *reinterpret_cast<const unsigned*>(ar0);
            unsigned a1 = *reinterpret_cast<const unsigned*>(ar1);
            unsigned a2 = *reinterpret_cast<const unsigned*>(ar0 + 8);
            unsigned a3 = *reinterpret_cast<const unsigned*>(ar1 + 8);

            #pragma unroll
            for (int nt = 0; nt < 8; ++nt) {
                const __half* br = &Wt[nt * 8 + gr][kc + ks * 16 + qp * 2];
                unsigned b0 = *reinterpret_cast<const unsigned*>(br);
                unsigned b1 = *reinterpret_cast<const unsigned*>(br + 8);
                asm volatile(
                    "mma.sync.aligned.m16n8k16.row.col.f32.f16.f16.f32 "
                    "{%0,%1,%2,%3}, {%4,%5,%6,%7}, {%8,%9}, {%0,%1,%2,%3};"
                    : "+f"(acc[nt][0]), "+f"(acc[nt][1]),
                      "+f"(acc[nt][2]), "+f"(acc[nt][3])
                    : "r"(a0), "r"(a1), "r"(a2), "r"(a3), "r"(b0), "r"(b1));
            }
        }
    }

    int r0 = block_row + w * 16 + gr;
    int r1 = r0 + 8;
    float ds0 = (r0 < n) ? g_dis[r0] : 0.f;
    float ds1 = (r1 < n) ? g_dis[r1] : 0.f;
    #pragma unroll
    for (int nt = 0; nt < 8; ++nt) {
        int c = nt * 8 + qp * 2;
        if (r0 < n)
            *reinterpret_cast<__half2*>(hout + (size_t)r0 * HID + c) =
                __floats2half2_rn(acc[nt][0] * ds0, acc[nt][1] * ds0);
        if (r1 < n)
            *reinterpret_cast<__half2*>(hout + (size_t)r1 * HID + c) =
                __floats2half2_rn(acc[nt][2] * ds1, acc[nt][3] * ds1);
    }
}

// ---------------------------------------------------------------------------
// CSR aggregation, fp16 gather / fp32 accumulate, paired edges with 4
// gathers in flight (8 edges/iter). Output fp16.
//   out[d] = relu( (h[d] + sum_{s in row(d)} h[s]) * dis[d] + b )
__global__ void agg_csr(const __half* __restrict__ h,
                        const float* __restrict__ bias,
                        __half* __restrict__ out,
                        int n)
{
    int warp = (blockIdx.x * blockDim.x + threadIdx.x) >> 5;
    int lane = threadIdx.x & 31;
    if (warp >= n) return;

    const uint2* hp = reinterpret_cast<const uint2*>(h);   // node row = 16 uint2
    int half = lane >> 4;
    int ch   = lane & 15;

    float4 acc = make_float4(0.f, 0.f, 0.f, 0.f);
#define ADDV(v) do {                                                   \
        __half2 _h0 = *reinterpret_cast<const __half2*>(&(v).x);      \
        __half2 _h1 = *reinterpret_cast<const __half2*>(&(v).y);      \
        float2 _f0 = __half22float2(_h0), _f1 = __half22float2(_h1);  \
        acc.x += _f0.x; acc.y += _f0.y; acc.z += _f1.x; acc.w += _f1.y; \
    } while (0)

    if (half == 0) { uint2 sv = hp[(size_t)warp * 16 + ch]; ADDV(sv); }

    int beg = g_rowst[warp];
    int end = beg + g_count[warp];

    int j = beg;
    for (; j + 7 < end; j += 8) {             // 4 paired gathers in flight
        int s0 = g_ssrc[j + half];
        int s1 = g_ssrc[j + 2 + half];
        int s2 = g_ssrc[j + 4 + half];
        int s3 = g_ssrc[j + 6 + half];
        uint2 v0 = hp[(size_t)s0 * 16 + ch];
        uint2 v1 = hp[(size_t)s1 * 16 + ch];
        uint2 v2 = hp[(size_t)s2 * 16 + ch];
        uint2 v3 = hp[(size_t)s3 * 16 + ch];
        ADDV(v0); ADDV(v1); ADDV(v2); ADDV(v3);
    }
    for (; j + 3 < end; j += 4) {
        int s0 = g_ssrc[j + half];
        int s1 = g_ssrc[j + 2 + half];
        uint2 v0 = hp[(size_t)s0 * 16 + ch];
        uint2 v1 = hp[(size_t)s1 * 16 + ch];
        ADDV(v0); ADDV(v1);
    }
    for (; j < end; j += 2) {
        int idx = j + half;
        if (idx < end) {
            int s = g_ssrc[idx];
            uint2 v = hp[(size_t)s * 16 + ch];
            ADDV(v);
        }
    }
#undef ADDV

    acc.x += __shfl_xor_sync(0xffffffffu, acc.x, 16);
    acc.y += __shfl_xor_sync(0xffffffffu, acc.y, 16);
    acc.z += __shfl_xor_sync(0xffffffffu, acc.z, 16);
    acc.w += __shfl_xor_sync(0xffffffffu, acc.w, 16);

    if (half == 0) {
        float ds = g_dis[warp];
        float4 b = __ldg(&reinterpret_cast<const float4*>(bias)[ch]);
        __half2 h0 = __floats2half2_rn(fmaxf(fmaf(acc.x, ds, b.x), 0.f),
                                       fmaxf(fmaf(acc.y, ds, b.y), 0.f));
        __half2 h1 = __floats2half2_rn(fmaxf(fmaf(acc.z, ds, b.z), 0.f),
                                       fmaxf(fmaf(acc.w, ds, b.w), 0.f));
        uint2 st;
        st.x = *reinterpret_cast<unsigned*>(&h0);
        st.y = *reinterpret_cast<unsigned*>(&h1);
        reinterpret_cast<uint2*>(out)[(size_t)warp * 16 + ch] = st;
    }
}

// ---------------------------------------------------------------------------
// Pool over sorted batch (fp16 input, fp32 output): one block per graph.
__global__ void pool_kernel(const __half* __restrict__ o2,
                            float* __restrict__ out,
                            int n)
{
    int g = blockIdx.x;
    int c = threadIdx.x;                       // 64 threads = 64 channels

    int lo = 0, hi = n;
    while (lo < hi) { int m = (lo + hi) >> 1; if (g_batch[m] < g) lo = m + 1; else hi = m; }
    int start = lo;
    hi = n;
    while (lo < hi) { int m = (lo + hi) >> 1; if (g_batch[m] < g + 1) lo = m + 1; else hi = m; }
    int end = lo;

    float sum = 0.f;
    int i = start;
    for (; i + 3 < end; i += 4) {
        float a0 = __half2float(o2[(size_t)i * HID + c]);
        float a1 = __half2float(o2[(size_t)(i + 1) * HID + c]);
        float a2 = __half2float(o2[(size_t)(i + 2) * HID + c]);
        float a3 = __half2float(o2[(size_t)(i + 3) * HID + c]);
        sum += (a0 + a1) + (a2 + a3);
    }
    for (; i < end; ++i) sum += __half2float(o2[(size_t)i * HID + c]);

    out[g * HID + c] = sum / (float)max(end - start, 1);
}

// ---------------------------------------------------------------------------
extern "C" void kernel_launch(void* const* d_in, const int* in_sizes, int n_in,
                              void* d_out, int out_size)
{
    const float* x  = nullptr;
    const void  *ei = nullptr, *bt = nullptr;
    const float *W1 = nullptr, *W2 = nullptr, *b1 = nullptr, *b2 = nullptr;
    int n = 0, e = 0;

    long long maxsz = 0;
    for (int i = 0; i < n_in; ++i) if (in_sizes[i] > maxsz) maxsz = in_sizes[i];
    for (int i = 0; i < n_in; ++i)
        if (in_sizes[i] == maxsz && !x) { x = (const float*)d_in[i]; n = (int)(maxsz / 128); }
    for (int i = 0; i < n_in; ++i) {
        long long sz = in_sizes[i];
        const void* p = d_in[i];
        if (p == (const void*)x) continue;
        if (sz == (long long)n)      { bt = p; }
        else if (sz > (long long)n)  { ei = p; e = (int)(sz / 2); }
        else if (sz == 128 * 64)     { W1 = (const float*)p; }
        else if (sz == 64 * 64)      { W2 = (const float*)p; }
        else if (sz == 64)           { if (!b1) b1 = (const float*)p; else b2 = (const float*)p; }
    }

    float* out = (float*)d_out;
    const int ng = out_size / HID;

    __half *ph, *po1, *po2;
    cudaGetSymbolAddress((void**)&ph,  g_h);
    cudaGetSymbolAddress((void**)&po1, g_o1);
    cudaGetSymbolAddress((void**)&po2, g_o2);

    const int T = 256;
    const int nb = (n + SCAN_B - 1) / SCAN_B;
    const int gb = (n + 127) / 128;            // GEMM blocks (128 rows each)
    const int e2 = (e + 1) / 2;                // vectorized pair count
    const int cthreads = ((e & 1) == 0) ? e2 : e;   // convert/scatter thread count
    const int cgrid = ((cthreads > n ? cthreads : n) + T - 1) / T;

    probe_init    <<<(n + T - 1) / T, T>>>((const unsigned*)ei, 2 * e,
                                           (const unsigned*)bt, n, n);
    convert_kernel<<<cgrid, T>>>(ei, e, bt, n);
    scan_a        <<<nb, SCAN_B>>>(n);                          // writes g_dis

    gcn_gemm<128, false><<<gb, 256>>>(x, W1, ph, n);            // reads g_dis

    scan_c<<<nb, SCAN_B>>>(n);
    scatter_kernel<<<(cthreads + T - 1) / T, T>>>(ei, e, n);

    agg_csr<<<(n * 32 + T - 1) / T, T>>>(ph, b1, po1, n);

    gcn_gemm<64, true><<<gb, 256>>>(po1, W2, ph, n);
    agg_csr<<<(n * 32 + T - 1) / T, T>>>(ph, b2, po2, n);

    pool_kernel<<<ng, HID>>>(po2, out, n);
}